// round 10
// baseline (speedup 1.0000x reference)
#include <cuda_runtime.h>
#include <math.h>

#define SEQ   2048
#define HIDN  4096
#define NHEAD 32
#define NKVH  8
#define HDIM  128
#define KVD   1024          // NKVH*HDIM
#define HEAVY 819           // int(1024*0.8)
#define RECENT 204          // int(1024*0.2)
#define NTOP  1844          // SEQ-RECENT
#define SP1   2049          // SEQ+1
#define ATT_SCALE 0.08838834764831843f

#define OUT0_ELEMS (SEQ * HIDN)            // 8388608 attn_output floats
#define OUT1_ELEMS (NHEAD * SP1)           // 65568 mask floats

// ---------------- scratch (device globals: allocation-free) ----------------
__device__ float g_Q[(size_t)SEQ * HIDN];
__device__ float g_K[(size_t)SEQ * KVD];
__device__ float g_V[(size_t)SEQ * KVD];
__device__ float g_Q2[(size_t)SEQ * HIDN];          // roped Q (new buffer)
__device__ float g_K2[(size_t)SEQ * KVD];           // roped K (new buffer)
__device__ float g_AO[(size_t)SEQ * HIDN];
__device__ float g_colsum[NHEAD * SEQ];
__device__ float g_sink[SEQ * HIDN];
__device__ float g_S[(size_t)NHEAD * SEQ * SEQ];    // attn weights scratch

// ---------------- naive 16x16 textbook gemm: C = A @ B --------------------
__global__ void gemm16(const float* __restrict__ A, const float* __restrict__ B,
                       float* __restrict__ C, int M, int N, int K) {
    __shared__ float As[16][16];
    __shared__ float Bs[16][17];
    int tx = threadIdx.x, ty = threadIdx.y;
    int m = blockIdx.y * 16 + ty;
    int n = blockIdx.x * 16 + tx;
    float acc = 0.0f;
    for (int k0 = 0; k0 < K; k0 += 16) {
        As[ty][tx] = A[(size_t)m * K + k0 + tx];
        Bs[ty][tx] = B[(size_t)(k0 + ty) * N + n];
        __syncthreads();
#pragma unroll
        for (int kk = 0; kk < 16; kk++) acc = fmaf(As[ty][kk], Bs[kk][tx], acc);
        __syncthreads();
    }
    C[(size_t)m * N + n] = acc;
}

// ---------------- RoPE v2: fresh impl, out-of-place, fp64 trig ------------
// grid (SEQ, NHEAD+NKVH), 64 threads; thread i handles pair (i, i+64).
__global__ void rope2_kernel() {
    int s  = blockIdx.x;
    int hh = blockIdx.y;
    int i  = threadIdx.x;              // 0..63 pair index
    // reference: inv_freq = 1/theta^(i/64) in f32; freqs = f32(p)*inv_freq
    float invf = (float)pow(10000.0, -(double)i / 64.0);   // best-f32 invf
    float ang  = (float)s * invf;                          // f32 product (ref order)
    float c  = (float)cos((double)ang);                    // exact trig of f32 angle
    float sn = (float)sin((double)ang);
    const float* src;
    float* dst;
    if (hh < NHEAD) {
        src = g_Q  + (size_t)s * HIDN + hh * HDIM;
        dst = g_Q2 + (size_t)s * HIDN + hh * HDIM;
    } else {
        src = g_K  + (size_t)s * KVD + (hh - NHEAD) * HDIM;
        dst = g_K2 + (size_t)s * KVD + (hh - NHEAD) * HDIM;
    }
    float x0 = src[i], x1 = src[i + 64];
    dst[i]      = x0 * c - x1 * sn;    // q*cos + rotate_half(q)*sin, lower half
    dst[i + 64] = x1 * c + x0 * sn;    // upper half
}

// ---------------- NAIVE scores v2: reads K2 directly (no transpose) -------
__global__ void scores_naive2() {
    int k = blockIdx.x * 256 + threadIdx.x;
    int q = blockIdx.y, h = blockIdx.z;
    if (k > q) return;                      // softmax zero-fills k>q
    const float* qrow = g_Q2 + (size_t)q * HIDN + h * HDIM;
    const float* krow = g_K2 + (size_t)k * KVD + (h >> 2) * HDIM;
    float acc = 0.0f;
#pragma unroll 8
    for (int d = 0; d < HDIM; d++)
        acc = fmaf(qrow[d], krow[d], acc);
    g_S[((size_t)h * SEQ + q) * SEQ + k] = acc * ATT_SCALE;
}

// ---------------- NAIVE softmax: one thread per (h,q) row -----------------
__global__ void softmax_naive() {
    int idx = blockIdx.x * blockDim.x + threadIdx.x;
    if (idx >= NHEAD * SEQ) return;
    int h = idx >> 11;
    int q = idx & (SEQ - 1);
    float* row = g_S + ((size_t)h * SEQ + q) * SEQ;
    float m = -INFINITY;
    for (int i = 0; i <= q; i++) m = fmaxf(m, row[i]);
    float s = 0.0f;
    for (int i = 0; i <= q; i++) {
        float e = expf(row[i] - m);
        row[i] = e;
        s += e;
    }
    float inv = 1.0f / s;
    for (int i = 0; i <= q; i++) row[i] *= inv;
    for (int i = q + 1; i < SEQ; i++) row[i] = 0.0f;
}

// ---------------- per-head column sums of attn weights --------------------
__global__ void colsum_kernel() {
    int idx = blockIdx.x * blockDim.x + threadIdx.x;
    int h = idx >> 11;
    int k = idx & (SEQ - 1);
    const float* base = g_S + (size_t)h * SEQ * SEQ + k;
    float s = 0.0f;
    for (int q = k; q < SEQ; q++) s += base[(size_t)q * SEQ];
    g_colsum[idx] = s;
}

// ---------------- NAIVE AV: one thread per (h,q,d) ------------------------
__global__ void av_naive() {
    int d = threadIdx.x;                   // 0..127
    int q = blockIdx.x, h = blockIdx.y;
    const float* w = g_S + ((size_t)h * SEQ + q) * SEQ;
    const float* v = g_V + (h >> 2) * HDIM + d;
    float acc = 0.0f;
    for (int k = 0; k <= q; k++)
        acc = fmaf(w[k], v[(size_t)k * KVD], acc);
    g_AO[(size_t)q * HIDN + h * HDIM + d] = acc;
}

// ---------------- top-k heavy-hitter mask (bitonic full sort) -------------
__global__ void topk_mask_kernel(float* __restrict__ out_mask) {
    __shared__ float sv[2048];
    __shared__ int   si[2048];
    int h = blockIdx.x;
    int t = threadIdx.x;
    for (int i = t; i < 2048; i += 1024) {
        sv[i] = (i < NTOP) ? g_colsum[h * SEQ + i] : -INFINITY;
        si[i] = i;
    }
    __syncthreads();
    for (int k = 2; k <= 2048; k <<= 1) {
        for (int j = k >> 1; j > 0; j >>= 1) {
            for (int i = t; i < 2048; i += 1024) {
                int ixj = i ^ j;
                if (ixj > i) {
                    bool dirDesc = ((i & k) == 0);
                    float v1 = sv[i], v2 = sv[ixj];
                    int i1 = si[i], i2 = si[ixj];
                    bool before = (v1 > v2) || (v1 == v2 && i1 < i2);
                    bool doSwap = dirDesc ? !before : before;
                    if (doSwap) { sv[i] = v2; sv[ixj] = v1; si[i] = i2; si[ixj] = i1; }
                }
            }
            __syncthreads();
        }
    }
    for (int j = t; j < SP1; j += 1024)
        out_mask[(size_t)h * SP1 + j] = (j >= SP1 - RECENT) ? 1.0f : 0.0f;
    __syncthreads();
    for (int r = t; r < HEAVY; r += 1024)
        out_mask[(size_t)h * SP1 + si[r]] = 1.0f;
}

// ---------------- launch --------------------------------------------------
extern "C" void kernel_launch(void* const* d_in, const int* in_sizes, int n_in,
                              void* d_out, int out_size) {
    // Binding proven correct (R4==R5): dict order; size-scan kept for safety.
    const float *hidden = 0, *Wq = 0, *Wk = 0, *Wv = 0, *Wo = 0;
    for (int i = 0; i < n_in; i++) {
        int sz = in_sizes[i];
        const float* p = (const float*)d_in[i];
        if (sz == SEQ * HIDN)            { hidden = p; }
        else if (sz == HIDN * HIDN)      { if (!Wq) Wq = p; else Wo = p; }
        else if (sz == HIDN * KVD)       { if (!Wk) Wk = p; else Wv = p; }
    }

    float *pQ, *pK, *pV, *pAO, *pSink;
    cudaGetSymbolAddress((void**)&pQ,  g_Q);
    cudaGetSymbolAddress((void**)&pK,  g_K);
    cudaGetSymbolAddress((void**)&pV,  g_V);
    cudaGetSymbolAddress((void**)&pAO, g_AO);
    cudaGetSymbolAddress((void**)&pSink, g_sink);

    // Output packing proven (R7): [attn | mask], attn at head.
    float* attn_dst = (float*)d_out;
    float* mask_dst;
    if (out_size == OUT0_ELEMS || out_size == OUT0_ELEMS * 4) {
        mask_dst = pSink;
    } else if (out_size == OUT1_ELEMS || out_size == OUT1_ELEMS * 4) {
        attn_dst = pSink;
        mask_dst = (float*)d_out;
    } else {
        mask_dst = (float*)d_out + OUT0_ELEMS;
    }

    dim3 blk16(16, 16);

    // 1-3. QKV projections (naive 16x16 gemm — cross-validated)
    gemm16<<<dim3(HIDN / 16, SEQ / 16), blk16>>>(hidden, Wq, pQ, SEQ, HIDN, HIDN);
    gemm16<<<dim3(KVD / 16,  SEQ / 16), blk16>>>(hidden, Wk, pK, SEQ, KVD, HIDN);
    gemm16<<<dim3(KVD / 16,  SEQ / 16), blk16>>>(hidden, Wv, pV, SEQ, KVD, HIDN);

    // 4. RoPE v2 (out-of-place, fp64 trig) -> g_Q2 / g_K2
    rope2_kernel<<<dim3(SEQ, NHEAD + NKVH), 64>>>();

    // 5. scores v2 (no transpose; direct K2 reads)
    scores_naive2<<<dim3(SEQ / 256, SEQ, NHEAD), 256>>>();

    // 6. causal softmax (naive per-row)
    softmax_naive<<<(NHEAD * SEQ + 255) / 256, 256>>>();

    // 7. column sums
    colsum_kernel<<<(NHEAD * SEQ) / 256, 256>>>();

    // 8. AV (naive per-(q,d))
    av_naive<<<dim3(SEQ, NHEAD), HDIM>>>();

    // 9. heavy-hitter mask
    topk_mask_kernel<<<NHEAD, 1024>>>(mask_dst);

    // 10. output projection (naive 16x16 gemm)
    gemm16<<<dim3(HIDN / 16, SEQ / 16), blk16>>>(pAO, Wo, attn_dst, SEQ, HIDN, HIDN);
}

// round 12
// speedup vs baseline: 6.4363x; 6.4363x over previous
#include <cuda_runtime.h>
#include <math.h>

#define SEQ   2048
#define HIDN  4096
#define NHEAD 32
#define NKVH  8
#define HDIM  128
#define KVD   1024          // NKVH*HDIM
#define HEAVY 819           // int(1024*0.8)
#define RECENT 204          // int(1024*0.2)
#define NTOP  1844          // SEQ-RECENT
#define SP1   2049          // SEQ+1
#define ATT_SCALE 0.08838834764831843f

#define OUT0_ELEMS (SEQ * HIDN)            // 8388608 attn_output floats
#define OUT1_ELEMS (NHEAD * SP1)           // 65568 mask floats

// ---------------- scratch (device globals: allocation-free) ----------------
__device__ float g_Q[(size_t)SEQ * HIDN];
__device__ float g_K[(size_t)SEQ * KVD];
__device__ float g_V[(size_t)SEQ * KVD];
__device__ float g_Q2[(size_t)SEQ * HIDN];          // roped Q
__device__ float g_K2[(size_t)SEQ * KVD];           // roped K
__device__ float g_AO[(size_t)SEQ * HIDN];
__device__ float g_colsum[NHEAD * SEQ];
__device__ float g_sink[SEQ * HIDN];
__device__ float g_S[(size_t)NHEAD * SEQ * SEQ];    // attn weights scratch

// ---------------- fast SGEMM: 128x128 tile, BK=8, 8x8/thread ---------------
// C[z][M,N] = alpha * A[z][M,K] @ B[z/bzDiv][K,N]  (row-major, ld strides)
// mode 0: plain.  mode 2: causal AV (K loop limited to (by+1)*128).
__global__ void sgemm_ld(const float* __restrict__ A, int lda, long long aZ,
                         const float* __restrict__ B, int ldb, long long bZ, int bzDiv,
                         float* __restrict__ C, int ldc, long long cZ,
                         int M, int N, int K, float alpha, int mode) {
    int bx = blockIdx.x, by = blockIdx.y, bz = blockIdx.z;
    int Keff = K;
    if (mode == 2) { int kl = (by + 1) * 128; if (kl < K) Keff = kl; }

    A += (size_t)bz * aZ;
    B += (size_t)(bz / bzDiv) * bZ;
    C += (size_t)bz * cZ;

    __shared__ float As[8][128];
    __shared__ float Bs[8][128];
    int tid = threadIdx.x;
    const float* Ab = A + (size_t)(by * 128) * lda;
    const float* Bb = B + bx * 128;
    int a_row = tid >> 1;
    int a_col = (tid & 1) * 4;
    int b_row = tid >> 5;
    int b_col = (tid & 31) * 4;
    int ty = tid >> 4, tx = tid & 15;
    float acc[8][8];
#pragma unroll
    for (int i = 0; i < 8; i++)
#pragma unroll
        for (int j = 0; j < 8; j++) acc[i][j] = 0.f;

    for (int k0 = 0; k0 < Keff; k0 += 8) {
        float4 av = *(const float4*)(Ab + (size_t)a_row * lda + k0 + a_col);
        As[a_col + 0][a_row] = av.x;
        As[a_col + 1][a_row] = av.y;
        As[a_col + 2][a_row] = av.z;
        As[a_col + 3][a_row] = av.w;
        float4 bv = *(const float4*)(Bb + (size_t)(k0 + b_row) * ldb + b_col);
        *(float4*)&Bs[b_row][b_col] = bv;
        __syncthreads();
#pragma unroll
        for (int kk = 0; kk < 8; kk++) {
            float ra[8], rb[8];
#pragma unroll
            for (int i = 0; i < 8; i++) ra[i] = As[kk][ty * 8 + i];
#pragma unroll
            for (int j = 0; j < 8; j++) rb[j] = Bs[kk][tx * 8 + j];
#pragma unroll
            for (int i = 0; i < 8; i++)
#pragma unroll
                for (int j = 0; j < 8; j++) acc[i][j] = fmaf(ra[i], rb[j], acc[i][j]);
        }
        __syncthreads();
    }
    float* Cb = C + (size_t)(by * 128 + ty * 8) * ldc + bx * 128 + tx * 8;
#pragma unroll
    for (int i = 0; i < 8; i++)
#pragma unroll
        for (int j = 0; j < 8; j++) Cb[(size_t)i * ldc + j] = alpha * acc[i][j];
}

// ---------------- RoPE v2 (FROZEN — proven correct in R9) ------------------
__global__ void rope2_kernel() {
    int s  = blockIdx.x;
    int hh = blockIdx.y;
    int i  = threadIdx.x;              // 0..63 pair index
    float invf = (float)pow(10000.0, -(double)i / 64.0);
    float ang  = (float)s * invf;
    float c  = (float)cos((double)ang);
    float sn = (float)sin((double)ang);
    const float* src;
    float* dst;
    if (hh < NHEAD) {
        src = g_Q  + (size_t)s * HIDN + hh * HDIM;
        dst = g_Q2 + (size_t)s * HIDN + hh * HDIM;
    } else {
        src = g_K  + (size_t)s * KVD + (hh - NHEAD) * HDIM;
        dst = g_K2 + (size_t)s * KVD + (hh - NHEAD) * HDIM;
    }
    float x0 = src[i], x1 = src[i + 64];
    dst[i]      = x0 * c - x1 * sn;
    dst[i + 64] = x1 * c + x0 * sn;
}

// ---------------- tiled scores: S[h][q][k] = scale*Q2_h[q]·K2_h[k] --------
// 64x64 tile, BK=16, 256 threads, 4x4/thread. K2 read directly (no transpose).
__global__ void scores_tiled() {
    int kt = blockIdx.x, qt = blockIdx.y, h = blockIdx.z;
    if (kt > qt) return;                  // fully above causal diagonal
    __shared__ float Qs[16][65];
    __shared__ float Ks[16][65];
    const float* Qb = g_Q2 + (size_t)qt * 64 * HIDN + h * HDIM;
    const float* Kb = g_K2 + (size_t)kt * 64 * KVD + (h >> 2) * HDIM;
    int tid = threadIdx.x;
    int lr = tid >> 2;          // 0..63 row within tile
    int lc = (tid & 3) * 4;     // 0,4,8,12 d-offset
    int tq = (tid >> 4) * 4;    // q offset of 4x4 micro tile
    int tk = (tid & 15) * 4;    // k offset
    float acc[4][4];
#pragma unroll
    for (int i = 0; i < 4; i++)
#pragma unroll
        for (int j = 0; j < 4; j++) acc[i][j] = 0.f;

    for (int d0 = 0; d0 < HDIM; d0 += 16) {
        float4 qv = *(const float4*)(Qb + (size_t)lr * HIDN + d0 + lc);
        Qs[lc + 0][lr] = qv.x; Qs[lc + 1][lr] = qv.y;
        Qs[lc + 2][lr] = qv.z; Qs[lc + 3][lr] = qv.w;
        float4 kv = *(const float4*)(Kb + (size_t)lr * KVD + d0 + lc);
        Ks[lc + 0][lr] = kv.x; Ks[lc + 1][lr] = kv.y;
        Ks[lc + 2][lr] = kv.z; Ks[lc + 3][lr] = kv.w;
        __syncthreads();
#pragma unroll
        for (int d = 0; d < 16; d++) {
            float ra[4], rb[4];
#pragma unroll
            for (int i = 0; i < 4; i++) ra[i] = Qs[d][tq + i];
#pragma unroll
            for (int j = 0; j < 4; j++) rb[j] = Ks[d][tk + j];
#pragma unroll
            for (int i = 0; i < 4; i++)
#pragma unroll
                for (int j = 0; j < 4; j++) acc[i][j] = fmaf(ra[i], rb[j], acc[i][j]);
        }
        __syncthreads();
    }
#pragma unroll
    for (int i = 0; i < 4; i++) {
        int q = qt * 64 + tq + i;
        float* row = g_S + ((size_t)h * SEQ + q) * SEQ + kt * 64 + tk;
#pragma unroll
        for (int j = 0; j < 4; j++) row[j] = acc[i][j] * ATT_SCALE;
    }
}

// ---------------- causal softmax per row (256 threads), zero-fill k>q -----
__global__ void softmax_tiled() {
    int q = blockIdx.x, h = blockIdx.y;
    float* row = g_S + ((size_t)h * SEQ + q) * SEQ;
    int len = q + 1;
    int t = threadIdx.x;
    __shared__ float red[256];
    float m = -INFINITY;
    for (int i = t; i < len; i += 256) m = fmaxf(m, row[i]);
    red[t] = m; __syncthreads();
    for (int sft = 128; sft > 0; sft >>= 1) {
        if (t < sft) red[t] = fmaxf(red[t], red[t + sft]);
        __syncthreads();
    }
    m = red[0]; __syncthreads();
    float sum = 0.f;
    for (int i = t; i < len; i += 256) {
        float e = expf(row[i] - m);
        row[i] = e;
        sum += e;
    }
    red[t] = sum; __syncthreads();
    for (int sft = 128; sft > 0; sft >>= 1) {
        if (t < sft) red[t] += red[t + sft];
        __syncthreads();
    }
    float inv = 1.0f / red[0];
    for (int i = t; i < len; i += 256) row[i] *= inv;
    for (int i = len + t; i < SEQ; i += 256) row[i] = 0.0f;
}

// ---------------- per-head column sums of attn weights --------------------
__global__ void colsum_kernel() {
    int idx = blockIdx.x * blockDim.x + threadIdx.x;
    int h = idx >> 11;
    int k = idx & (SEQ - 1);
    const float* base = g_S + (size_t)h * SEQ * SEQ + k;
    float s = 0.0f;
    for (int q = k; q < SEQ; q++) s += base[(size_t)q * SEQ];
    g_colsum[idx] = s;
}

// ---------------- top-k heavy-hitter mask (bitonic full sort) -------------
__global__ void topk_mask_kernel(float* __restrict__ out_mask) {
    __shared__ float sv[2048];
    __shared__ int   si[2048];
    int h = blockIdx.x;
    int t = threadIdx.x;
    for (int i = t; i < 2048; i += 1024) {
        sv[i] = (i < NTOP) ? g_colsum[h * SEQ + i] : -INFINITY;
        si[i] = i;
    }
    __syncthreads();
    for (int k = 2; k <= 2048; k <<= 1) {
        for (int j = k >> 1; j > 0; j >>= 1) {
            for (int i = t; i < 2048; i += 1024) {
                int ixj = i ^ j;
                if (ixj > i) {
                    bool dirDesc = ((i & k) == 0);
                    float v1 = sv[i], v2 = sv[ixj];
                    int i1 = si[i], i2 = si[ixj];
                    bool before = (v1 > v2) || (v1 == v2 && i1 < i2);
                    bool doSwap = dirDesc ? !before : before;
                    if (doSwap) { sv[i] = v2; sv[ixj] = v1; si[i] = i2; si[ixj] = i1; }
                }
            }
            __syncthreads();
        }
    }
    for (int j = t; j < SP1; j += 1024)
        out_mask[(size_t)h * SP1 + j] = (j >= SP1 - RECENT) ? 1.0f : 0.0f;
    __syncthreads();
    for (int r = t; r < HEAVY; r += 1024)
        out_mask[(size_t)h * SP1 + si[r]] = 1.0f;
}

// ---------------- launch --------------------------------------------------
extern "C" void kernel_launch(void* const* d_in, const int* in_sizes, int n_in,
                              void* d_out, int out_size) {
    const float *hidden = 0, *Wq = 0, *Wk = 0, *Wv = 0, *Wo = 0;
    for (int i = 0; i < n_in; i++) {
        int sz = in_sizes[i];
        const float* p = (const float*)d_in[i];
        if (sz == SEQ * HIDN)            { hidden = p; }
        else if (sz == HIDN * HIDN)      { if (!Wq) Wq = p; else Wo = p; }
        else if (sz == HIDN * KVD)       { if (!Wk) Wk = p; else Wv = p; }
    }

    float *pQ, *pK, *pV, *pAO, *pS, *pSink;
    cudaGetSymbolAddress((void**)&pQ,  g_Q);
    cudaGetSymbolAddress((void**)&pK,  g_K);
    cudaGetSymbolAddress((void**)&pV,  g_V);
    cudaGetSymbolAddress((void**)&pAO, g_AO);
    cudaGetSymbolAddress((void**)&pS,  g_S);
    cudaGetSymbolAddress((void**)&pSink, g_sink);

    // Output packing proven (R7): [attn | mask], attn at head.
    float* attn_dst = (float*)d_out;
    float* mask_dst;
    if (out_size == OUT0_ELEMS || out_size == OUT0_ELEMS * 4) {
        mask_dst = pSink;
    } else if (out_size == OUT1_ELEMS || out_size == OUT1_ELEMS * 4) {
        attn_dst = pSink;
        mask_dst = (float*)d_out;
    } else {
        mask_dst = (float*)d_out + OUT0_ELEMS;
    }

    // 1-3. QKV projections (fast tiled gemm)
    sgemm_ld<<<dim3(HIDN / 128, SEQ / 128, 1), 256>>>(
        hidden, HIDN, 0, Wq, HIDN, 0, 1, pQ, HIDN, 0, SEQ, HIDN, HIDN, 1.0f, 0);
    sgemm_ld<<<dim3(KVD / 128, SEQ / 128, 1), 256>>>(
        hidden, HIDN, 0, Wk, KVD, 0, 1, pK, KVD, 0, SEQ, KVD, HIDN, 1.0f, 0);
    sgemm_ld<<<dim3(KVD / 128, SEQ / 128, 1), 256>>>(
        hidden, HIDN, 0, Wv, KVD, 0, 1, pV, KVD, 0, SEQ, KVD, HIDN, 1.0f, 0);

    // 4. RoPE v2 (frozen)
    rope2_kernel<<<dim3(SEQ, NHEAD + NKVH), 64>>>();

    // 5. scores (tiled, K2 direct)
    scores_tiled<<<dim3(SEQ / 64, SEQ / 64, NHEAD), 256>>>();

    // 6. causal softmax (tiled)
    softmax_tiled<<<dim3(SEQ, NHEAD), 256>>>();

    // 7. column sums
    colsum_kernel<<<(NHEAD * SEQ) / 256, 256>>>();

    // 8. AV: AO_h = S_h @ V_h (tiled, causal K-limit)
    sgemm_ld<<<dim3(HDIM / 128, SEQ / 128, NHEAD), 256>>>(
        pS, SEQ, (long long)SEQ * SEQ,
        pV, KVD, HDIM, 4,
        pAO, HIDN, HDIM,
        SEQ, HDIM, SEQ, 1.0f, 2);

    // 9. heavy-hitter mask
    topk_mask_kernel<<<NHEAD, 1024>>>(mask_dst);

    // 10. output projection (fast tiled gemm)
    sgemm_ld<<<dim3(HIDN / 128, SEQ / 128, 1), 256>>>(
        pAO, HIDN, 0, Wo, HIDN, 0, 1, attn_dst, HIDN, 0, SEQ, HIDN, HIDN, 1.0f, 0);
}

// round 14
// speedup vs baseline: 10.2825x; 1.5976x over previous
#include <cuda_runtime.h>
#include <cuda_bf16.h>
#include <math.h>
#include <stdint.h>

#define SEQ   2048
#define HIDN  4096
#define NHEAD 32
#define NKVH  8
#define HDIM  128
#define KVD   1024          // NKVH*HDIM
#define HEAVY 819           // int(1024*0.8)
#define RECENT 204          // int(1024*0.2)
#define NTOP  1844          // SEQ-RECENT
#define SP1   2049          // SEQ+1
#define ATT_SCALE 0.08838834764831843f

#define OUT0_ELEMS (SEQ * HIDN)            // 8388608 attn_output floats
#define OUT1_ELEMS (NHEAD * SP1)           // 65568 mask floats

// ---------------- scratch (device globals: allocation-free) ----------------
__device__ float g_Q[(size_t)SEQ * HIDN];
__device__ float g_K[(size_t)SEQ * KVD];
__device__ float g_V[(size_t)SEQ * KVD];
__device__ float g_Q2[(size_t)SEQ * HIDN];          // roped Q
__device__ float g_K2[(size_t)SEQ * KVD];           // roped K
__device__ float g_AO[(size_t)SEQ * HIDN];
__device__ float g_colsum[NHEAD * SEQ];
__device__ float g_sink[SEQ * HIDN];
__device__ float g_S[(size_t)NHEAD * SEQ * SEQ];    // attn weights scratch

// bf16 split operands
__device__ __nv_bfloat16 g_Hhi[(size_t)SEQ * HIDN];
__device__ __nv_bfloat16 g_Hlo[(size_t)SEQ * HIDN];
__device__ __nv_bfloat16 g_AOhi[(size_t)SEQ * HIDN];
__device__ __nv_bfloat16 g_AOlo[(size_t)SEQ * HIDN];
__device__ __nv_bfloat16 g_WqThi[(size_t)HIDN * HIDN];   // [N, K] K-major
__device__ __nv_bfloat16 g_WqTlo[(size_t)HIDN * HIDN];
__device__ __nv_bfloat16 g_WkThi[(size_t)KVD * HIDN];
__device__ __nv_bfloat16 g_WkTlo[(size_t)KVD * HIDN];
__device__ __nv_bfloat16 g_WvThi[(size_t)KVD * HIDN];
__device__ __nv_bfloat16 g_WvTlo[(size_t)KVD * HIDN];
__device__ __nv_bfloat16 g_WoThi[(size_t)HIDN * HIDN];
__device__ __nv_bfloat16 g_WoTlo[(size_t)HIDN * HIDN];

// ---------------- mma helpers ----------------------------------------------
__device__ __forceinline__ void ldsm_x4(uint32_t& r0, uint32_t& r1,
                                        uint32_t& r2, uint32_t& r3, uint32_t addr) {
    asm volatile("ldmatrix.sync.aligned.m8n8.x4.shared.b16 {%0,%1,%2,%3}, [%4];"
                 : "=r"(r0), "=r"(r1), "=r"(r2), "=r"(r3) : "r"(addr));
}
__device__ __forceinline__ void ldsm_x2(uint32_t& r0, uint32_t& r1, uint32_t addr) {
    asm volatile("ldmatrix.sync.aligned.m8n8.x2.shared.b16 {%0,%1}, [%2];"
                 : "=r"(r0), "=r"(r1) : "r"(addr));
}
__device__ __forceinline__ void mma_bf16(float* d, const uint32_t* a, const uint32_t* b) {
    asm volatile(
        "mma.sync.aligned.m16n8k16.row.col.f32.bf16.bf16.f32 "
        "{%0,%1,%2,%3}, {%4,%5,%6,%7}, {%8,%9}, {%0,%1,%2,%3};"
        : "+f"(d[0]), "+f"(d[1]), "+f"(d[2]), "+f"(d[3])
        : "r"(a[0]), "r"(a[1]), "r"(a[2]), "r"(a[3]), "r"(b[0]), "r"(b[1]));
}

// ---------------- fused split-bf16 tensor-core GEMM ------------------------
// C[m,n] = sum_k (Ahi+Alo)[m,k] * (Bhi+Blo)[n,k]  (lo*lo dropped)
// A tiles [M,K] K-major, B tiles [N,K] K-major. 128x128/CTA, K-chunk 32.
#define LDS 40   // smem row stride in bf16 elements (32 + 8 pad)
__global__ void __launch_bounds__(256) mma3gemm(
    const __nv_bfloat16* __restrict__ Ahi, const __nv_bfloat16* __restrict__ Alo,
    const __nv_bfloat16* __restrict__ Bhi, const __nv_bfloat16* __restrict__ Blo,
    float* __restrict__ C, int K, int ldc)
{
    __shared__ __nv_bfloat16 sAhi[128 * LDS];
    __shared__ __nv_bfloat16 sAlo[128 * LDS];
    __shared__ __nv_bfloat16 sBhi[128 * LDS];
    __shared__ __nv_bfloat16 sBlo[128 * LDS];

    int tid  = threadIdx.x;
    int lane = tid & 31;
    int wid  = tid >> 5;
    int wm   = wid & 1;          // warp m block (0..1) -> 64 rows
    int wn   = wid >> 1;         // warp n block (0..3) -> 32 cols
    int m0 = blockIdx.y * 128;
    int n0 = blockIdx.x * 128;

    // gmem load mapping: row = tid/2 (0..127), col half = (tid&1)*16
    int lr = tid >> 1;
    int lc = (tid & 1) * 16;
    const __nv_bfloat16* gAhi = Ahi + (size_t)(m0 + lr) * K + lc;
    const __nv_bfloat16* gAlo = Alo + (size_t)(m0 + lr) * K + lc;
    const __nv_bfloat16* gBhi = Bhi + (size_t)(n0 + lr) * K + lc;
    const __nv_bfloat16* gBlo = Blo + (size_t)(n0 + lr) * K + lc;
    uint32_t so = (uint32_t)(lr * LDS + lc) * 2;   // byte offset in smem tile
    uint32_t bAhi = (uint32_t)__cvta_generic_to_shared(sAhi);
    uint32_t bAlo = (uint32_t)__cvta_generic_to_shared(sAlo);
    uint32_t bBhi = (uint32_t)__cvta_generic_to_shared(sBhi);
    uint32_t bBlo = (uint32_t)__cvta_generic_to_shared(sBlo);

    float d[4][4][4];            // [mt][nt][frag]
#pragma unroll
    for (int i = 0; i < 4; i++)
#pragma unroll
        for (int j = 0; j < 4; j++)
#pragma unroll
            for (int f = 0; f < 4; f++) d[i][j][f] = 0.f;

    // ldmatrix address offsets (within a tile): A uses lanes 0-31, B lanes 0-15
    int arow = wm * 64 + (lane & 15);            // + mt*16
    int acol = (lane >> 4) * 8;                  // + ks*16
    int brow = wn * 32 + (lane & 7);             // + nt*8
    int bcol = ((lane >> 3) & 1) * 8;            // + ks*16

    int nchunks = K / 32;
    for (int c = 0; c < nchunks; c++) {
        // stage 32-col chunk of all 4 tiles
        *(uint4*)((char*)sAhi + so)      = *(const uint4*)(gAhi);
        *(uint4*)((char*)sAhi + so + 16) = *(const uint4*)(gAhi + 8);
        *(uint4*)((char*)sAlo + so)      = *(const uint4*)(gAlo);
        *(uint4*)((char*)sAlo + so + 16) = *(const uint4*)(gAlo + 8);
        *(uint4*)((char*)sBhi + so)      = *(const uint4*)(gBhi);
        *(uint4*)((char*)sBhi + so + 16) = *(const uint4*)(gBhi + 8);
        *(uint4*)((char*)sBlo + so)      = *(const uint4*)(gBlo);
        *(uint4*)((char*)sBlo + so + 16) = *(const uint4*)(gBlo + 8);
        gAhi += 32; gAlo += 32; gBhi += 32; gBlo += 32;
        __syncthreads();

#pragma unroll
        for (int ks = 0; ks < 2; ks++) {
            uint32_t bh[4][2], bl[4][2];
#pragma unroll
            for (int nt = 0; nt < 4; nt++) {
                uint32_t off = (uint32_t)((brow + nt * 8) * LDS + ks * 16 + bcol) * 2;
                ldsm_x2(bh[nt][0], bh[nt][1], bBhi + off);
                ldsm_x2(bl[nt][0], bl[nt][1], bBlo + off);
            }
#pragma unroll
            for (int mt = 0; mt < 4; mt++) {
                uint32_t off = (uint32_t)((arow + mt * 16) * LDS + ks * 16 + acol) * 2;
                uint32_t ah[4], al[4];
                ldsm_x4(ah[0], ah[1], ah[2], ah[3], bAhi + off);
                ldsm_x4(al[0], al[1], al[2], al[3], bAlo + off);
#pragma unroll
                for (int nt = 0; nt < 4; nt++) {
                    mma_bf16(d[mt][nt], ah, bh[nt]);   // hi*hi
                    mma_bf16(d[mt][nt], ah, bl[nt]);   // hi*lo
                    mma_bf16(d[mt][nt], al, bh[nt]);   // lo*hi
                }
            }
        }
        __syncthreads();
    }

    // epilogue: frag -> C
    int cr = lane >> 2;          // 0..7
    int cc = (lane & 3) * 2;
#pragma unroll
    for (int mt = 0; mt < 4; mt++) {
#pragma unroll
        for (int nt = 0; nt < 4; nt++) {
            float* base = C + (size_t)(m0 + wm * 64 + mt * 16 + cr) * ldc
                        + n0 + wn * 32 + nt * 8 + cc;
            base[0] = d[mt][nt][0];
            base[1] = d[mt][nt][1];
            base[(size_t)8 * ldc]     = d[mt][nt][2];
            base[(size_t)8 * ldc + 1] = d[mt][nt][3];
        }
    }
}

// ---------------- fp32 -> bf16 hi/lo split (elementwise) -------------------
__global__ void split_hl(const float* __restrict__ X,
                         __nv_bfloat16* __restrict__ Hi,
                         __nv_bfloat16* __restrict__ Lo, int n) {
    int i = blockIdx.x * blockDim.x + threadIdx.x;
    if (i >= n) return;
    float v = X[i];
    __nv_bfloat16 h = __float2bfloat16(v);
    Hi[i] = h;
    Lo[i] = __float2bfloat16(v - __bfloat162float(h));
}

// ---------------- W[K,N] -> WT[N,K] with hi/lo split -----------------------
__global__ void transpose_split(const float* __restrict__ W, int K, int N,
                                __nv_bfloat16* __restrict__ Thi,
                                __nv_bfloat16* __restrict__ Tlo) {
    __shared__ float t[32][33];
    int n0 = blockIdx.x * 32, k0 = blockIdx.y * 32;
    int tx = threadIdx.x, ty = threadIdx.y;
#pragma unroll
    for (int j = 0; j < 4; j++)
        t[ty + 8 * j][tx] = W[(size_t)(k0 + ty + 8 * j) * N + n0 + tx];
    __syncthreads();
#pragma unroll
    for (int j = 0; j < 4; j++) {
        float v = t[tx][ty + 8 * j];
        __nv_bfloat16 h = __float2bfloat16(v);
        size_t o = (size_t)(n0 + ty + 8 * j) * K + k0 + tx;
        Thi[o] = h;
        Tlo[o] = __float2bfloat16(v - __bfloat162float(h));
    }
}

// ---------------- fast fp32 SGEMM (kept for AV) ----------------------------
__global__ void sgemm_ld(const float* __restrict__ A, int lda, long long aZ,
                         const float* __restrict__ B, int ldb, long long bZ, int bzDiv,
                         float* __restrict__ C, int ldc, long long cZ,
                         int M, int N, int K, float alpha, int mode) {
    int bx = blockIdx.x, by = blockIdx.y, bz = blockIdx.z;
    int Keff = K;
    if (mode == 2) { int kl = (by + 1) * 128; if (kl < K) Keff = kl; }
    A += (size_t)bz * aZ;
    B += (size_t)(bz / bzDiv) * bZ;
    C += (size_t)bz * cZ;
    __shared__ float As[8][128];
    __shared__ float Bs[8][128];
    int tid = threadIdx.x;
    const float* Ab = A + (size_t)(by * 128) * lda;
    const float* Bb = B + bx * 128;
    int a_row = tid >> 1;
    int a_col = (tid & 1) * 4;
    int b_row = tid >> 5;
    int b_col = (tid & 31) * 4;
    int ty = tid >> 4, tx = tid & 15;
    float acc[8][8];
#pragma unroll
    for (int i = 0; i < 8; i++)
#pragma unroll
        for (int j = 0; j < 8; j++) acc[i][j] = 0.f;
    for (int k0 = 0; k0 < Keff; k0 += 8) {
        float4 av = *(const float4*)(Ab + (size_t)a_row * lda + k0 + a_col);
        As[a_col + 0][a_row] = av.x;
        As[a_col + 1][a_row] = av.y;
        As[a_col + 2][a_row] = av.z;
        As[a_col + 3][a_row] = av.w;
        float4 bv = *(const float4*)(Bb + (size_t)(k0 + b_row) * ldb + b_col);
        *(float4*)&Bs[b_row][b_col] = bv;
        __syncthreads();
#pragma unroll
        for (int kk = 0; kk < 8; kk++) {
            float ra[8], rb[8];
#pragma unroll
            for (int i = 0; i < 8; i++) ra[i] = As[kk][ty * 8 + i];
#pragma unroll
            for (int j = 0; j < 8; j++) rb[j] = Bs[kk][tx * 8 + j];
#pragma unroll
            for (int i = 0; i < 8; i++)
#pragma unroll
                for (int j = 0; j < 8; j++) acc[i][j] = fmaf(ra[i], rb[j], acc[i][j]);
        }
        __syncthreads();
    }
    float* Cb = C + (size_t)(by * 128 + ty * 8) * ldc + bx * 128 + tx * 8;
#pragma unroll
    for (int i = 0; i < 8; i++)
#pragma unroll
        for (int j = 0; j < 8; j++) Cb[(size_t)i * ldc + j] = alpha * acc[i][j];
}

// ---------------- RoPE v2 (FROZEN — proven correct in R9) ------------------
__global__ void rope2_kernel() {
    int s  = blockIdx.x;
    int hh = blockIdx.y;
    int i  = threadIdx.x;
    float invf = (float)pow(10000.0, -(double)i / 64.0);
    float ang  = (float)s * invf;
    float c  = (float)cos((double)ang);
    float sn = (float)sin((double)ang);
    const float* src;
    float* dst;
    if (hh < NHEAD) {
        src = g_Q  + (size_t)s * HIDN + hh * HDIM;
        dst = g_Q2 + (size_t)s * HIDN + hh * HDIM;
    } else {
        src = g_K  + (size_t)s * KVD + (hh - NHEAD) * HDIM;
        dst = g_K2 + (size_t)s * KVD + (hh - NHEAD) * HDIM;
    }
    float x0 = src[i], x1 = src[i + 64];
    dst[i]      = x0 * c - x1 * sn;
    dst[i + 64] = x1 * c + x0 * sn;
}

// ---------------- tiled scores (verified R11) ------------------------------
__global__ void scores_tiled() {
    int kt = blockIdx.x, qt = blockIdx.y, h = blockIdx.z;
    if (kt > qt) return;
    __shared__ float Qs[16][65];
    __shared__ float Ks[16][65];
    const float* Qb = g_Q2 + (size_t)qt * 64 * HIDN + h * HDIM;
    const float* Kb = g_K2 + (size_t)kt * 64 * KVD + (h >> 2) * HDIM;
    int tid = threadIdx.x;
    int lr = tid >> 2;
    int lc = (tid & 3) * 4;
    int tq = (tid >> 4) * 4;
    int tk = (tid & 15) * 4;
    float acc[4][4];
#pragma unroll
    for (int i = 0; i < 4; i++)
#pragma unroll
        for (int j = 0; j < 4; j++) acc[i][j] = 0.f;
    for (int d0 = 0; d0 < HDIM; d0 += 16) {
        float4 qv = *(const float4*)(Qb + (size_t)lr * HIDN + d0 + lc);
        Qs[lc + 0][lr] = qv.x; Qs[lc + 1][lr] = qv.y;
        Qs[lc + 2][lr] = qv.z; Qs[lc + 3][lr] = qv.w;
        float4 kv = *(const float4*)(Kb + (size_t)lr * KVD + d0 + lc);
        Ks[lc + 0][lr] = kv.x; Ks[lc + 1][lr] = kv.y;
        Ks[lc + 2][lr] = kv.z; Ks[lc + 3][lr] = kv.w;
        __syncthreads();
#pragma unroll
        for (int d = 0; d < 16; d++) {
            float ra[4], rb[4];
#pragma unroll
            for (int i = 0; i < 4; i++) ra[i] = Qs[d][tq + i];
#pragma unroll
            for (int j = 0; j < 4; j++) rb[j] = Ks[d][tk + j];
#pragma unroll
            for (int i = 0; i < 4; i++)
#pragma unroll
                for (int j = 0; j < 4; j++) acc[i][j] = fmaf(ra[i], rb[j], acc[i][j]);
        }
        __syncthreads();
    }
#pragma unroll
    for (int i = 0; i < 4; i++) {
        int q = qt * 64 + tq + i;
        float* row = g_S + ((size_t)h * SEQ + q) * SEQ + kt * 64 + tk;
#pragma unroll
        for (int j = 0; j < 4; j++) row[j] = acc[i][j] * ATT_SCALE;
    }
}

// ---------------- causal softmax (verified) --------------------------------
__global__ void softmax_tiled() {
    int q = blockIdx.x, h = blockIdx.y;
    float* row = g_S + ((size_t)h * SEQ + q) * SEQ;
    int len = q + 1;
    int t = threadIdx.x;
    __shared__ float red[256];
    float m = -INFINITY;
    for (int i = t; i < len; i += 256) m = fmaxf(m, row[i]);
    red[t] = m; __syncthreads();
    for (int sft = 128; sft > 0; sft >>= 1) {
        if (t < sft) red[t] = fmaxf(red[t], red[t + sft]);
        __syncthreads();
    }
    m = red[0]; __syncthreads();
    float sum = 0.f;
    for (int i = t; i < len; i += 256) {
        float e = expf(row[i] - m);
        row[i] = e;
        sum += e;
    }
    red[t] = sum; __syncthreads();
    for (int sft = 128; sft > 0; sft >>= 1) {
        if (t < sft) red[t] += red[t + sft];
        __syncthreads();
    }
    float inv = 1.0f / red[0];
    for (int i = t; i < len; i += 256) row[i] *= inv;
    for (int i = len + t; i < SEQ; i += 256) row[i] = 0.0f;
}

// ---------------- column sums (verified) -----------------------------------
__global__ void colsum_kernel() {
    int idx = blockIdx.x * blockDim.x + threadIdx.x;
    int h = idx >> 11;
    int k = idx & (SEQ - 1);
    const float* base = g_S + (size_t)h * SEQ * SEQ + k;
    float s = 0.0f;
    for (int q = k; q < SEQ; q++) s += base[(size_t)q * SEQ];
    g_colsum[idx] = s;
}

// ---------------- top-k heavy-hitter mask (verified) -----------------------
__global__ void topk_mask_kernel(float* __restrict__ out_mask) {
    __shared__ float sv[2048];
    __shared__ int   si[2048];
    int h = blockIdx.x;
    int t = threadIdx.x;
    for (int i = t; i < 2048; i += 1024) {
        sv[i] = (i < NTOP) ? g_colsum[h * SEQ + i] : -INFINITY;
        si[i] = i;
    }
    __syncthreads();
    for (int k = 2; k <= 2048; k <<= 1) {
        for (int j = k >> 1; j > 0; j >>= 1) {
            for (int i = t; i < 2048; i += 1024) {
                int ixj = i ^ j;
                if (ixj > i) {
                    bool dirDesc = ((i & k) == 0);
                    float v1 = sv[i], v2 = sv[ixj];
                    int i1 = si[i], i2 = si[ixj];
                    bool before = (v1 > v2) || (v1 == v2 && i1 < i2);
                    bool doSwap = dirDesc ? !before : before;
                    if (doSwap) { sv[i] = v2; sv[ixj] = v1; si[i] = i2; si[ixj] = i1; }
                }
            }
            __syncthreads();
        }
    }
    for (int j = t; j < SP1; j += 1024)
        out_mask[(size_t)h * SP1 + j] = (j >= SP1 - RECENT) ? 1.0f : 0.0f;
    __syncthreads();
    for (int r = t; r < HEAVY; r += 1024)
        out_mask[(size_t)h * SP1 + si[r]] = 1.0f;
}

// ---------------- launch --------------------------------------------------
extern "C" void kernel_launch(void* const* d_in, const int* in_sizes, int n_in,
                              void* d_out, int out_size) {
    const float *hidden = 0, *Wq = 0, *Wk = 0, *Wv = 0, *Wo = 0;
    for (int i = 0; i < n_in; i++) {
        int sz = in_sizes[i];
        const float* p = (const float*)d_in[i];
        if (sz == SEQ * HIDN)            { hidden = p; }
        else if (sz == HIDN * HIDN)      { if (!Wq) Wq = p; else Wo = p; }
        else if (sz == HIDN * KVD)       { if (!Wk) Wk = p; else Wv = p; }
    }

    float *pQ, *pK, *pV, *pAO, *pS, *pSink;
    cudaGetSymbolAddress((void**)&pQ,  g_Q);
    cudaGetSymbolAddress((void**)&pK,  g_K);
    cudaGetSymbolAddress((void**)&pV,  g_V);
    cudaGetSymbolAddress((void**)&pAO, g_AO);
    cudaGetSymbolAddress((void**)&pS,  g_S);
    cudaGetSymbolAddress((void**)&pSink, g_sink);

    __nv_bfloat16 *pHhi, *pHlo, *pAOhi, *pAOlo;
    __nv_bfloat16 *pWqThi, *pWqTlo, *pWkThi, *pWkTlo, *pWvThi, *pWvTlo, *pWoThi, *pWoTlo;
    cudaGetSymbolAddress((void**)&pHhi,  g_Hhi);
    cudaGetSymbolAddress((void**)&pHlo,  g_Hlo);
    cudaGetSymbolAddress((void**)&pAOhi, g_AOhi);
    cudaGetSymbolAddress((void**)&pAOlo, g_AOlo);
    cudaGetSymbolAddress((void**)&pWqThi, g_WqThi);
    cudaGetSymbolAddress((void**)&pWqTlo, g_WqTlo);
    cudaGetSymbolAddress((void**)&pWkThi, g_WkThi);
    cudaGetSymbolAddress((void**)&pWkTlo, g_WkTlo);
    cudaGetSymbolAddress((void**)&pWvThi, g_WvThi);
    cudaGetSymbolAddress((void**)&pWvTlo, g_WvTlo);
    cudaGetSymbolAddress((void**)&pWoThi, g_WoThi);
    cudaGetSymbolAddress((void**)&pWoTlo, g_WoTlo);

    // Output packing proven (R7): [attn | mask], attn at head.
    float* attn_dst = (float*)d_out;
    float* mask_dst;
    if (out_size == OUT0_ELEMS || out_size == OUT0_ELEMS * 4) {
        mask_dst = pSink;
    } else if (out_size == OUT1_ELEMS || out_size == OUT1_ELEMS * 4) {
        attn_dst = pSink;
        mask_dst = (float*)d_out;
    } else {
        mask_dst = (float*)d_out + OUT0_ELEMS;
    }

    dim3 tblk(32, 8);

    // 0. operand prep
    split_hl<<<(SEQ * HIDN + 255) / 256, 256>>>(hidden, pHhi, pHlo, SEQ * HIDN);
    transpose_split<<<dim3(HIDN / 32, HIDN / 32), tblk>>>(Wq, HIDN, HIDN, pWqThi, pWqTlo);
    transpose_split<<<dim3(KVD / 32,  HIDN / 32), tblk>>>(Wk, HIDN, KVD,  pWkThi, pWkTlo);
    transpose_split<<<dim3(KVD / 32,  HIDN / 32), tblk>>>(Wv, HIDN, KVD,  pWvThi, pWvTlo);
    transpose_split<<<dim3(HIDN / 32, HIDN / 32), tblk>>>(Wo, HIDN, HIDN, pWoThi, pWoTlo);

    // 1-3. QKV projections: fused 3-term split-bf16 tensor-core GEMM
    mma3gemm<<<dim3(HIDN / 128, SEQ / 128), 256>>>(pHhi, pHlo, pWqThi, pWqTlo, pQ, HIDN, HIDN);
    mma3gemm<<<dim3(KVD / 128,  SEQ / 128), 256>>>(pHhi, pHlo, pWkThi, pWkTlo, pK, HIDN, KVD);
    mma3gemm<<<dim3(KVD / 128,  SEQ / 128), 256>>>(pHhi, pHlo, pWvThi, pWvTlo, pV, HIDN, KVD);

    // 4. RoPE v2 (frozen)
    rope2_kernel<<<dim3(SEQ, NHEAD + NKVH), 64>>>();

    // 5. scores (tiled fp32)
    scores_tiled<<<dim3(SEQ / 64, SEQ / 64, NHEAD), 256>>>();

    // 6. causal softmax
    softmax_tiled<<<dim3(SEQ, NHEAD), 256>>>();

    // 7. column sums
    colsum_kernel<<<(NHEAD * SEQ) / 256, 256>>>();

    // 8. AV (fp32 tiled, causal K-limit)
    sgemm_ld<<<dim3(HDIM / 128, SEQ / 128, NHEAD), 256>>>(
        pS, SEQ, (long long)SEQ * SEQ,
        pV, KVD, HDIM, 4,
        pAO, HIDN, HDIM,
        SEQ, HDIM, SEQ, 1.0f, 2);

    // 9. heavy-hitter mask
    topk_mask_kernel<<<NHEAD, 1024>>>(mask_dst);

    // 10. output projection: split AO then fused MMA gemm
    split_hl<<<(SEQ * HIDN + 255) / 256, 256>>>(pAO, pAOhi, pAOlo, SEQ * HIDN);
    mma3gemm<<<dim3(HIDN / 128, SEQ / 128), 256>>>(pAOhi, pAOlo, pWoThi, pWoTlo,
                                                   attn_dst, HIDN, HIDN);
}

// round 15
// speedup vs baseline: 11.1250x; 1.0819x over previous
#include <cuda_runtime.h>
#include <cuda_bf16.h>
#include <math.h>
#include <stdint.h>

#define SEQ   2048
#define HIDN  4096
#define NHEAD 32
#define NKVH  8
#define HDIM  128
#define KVD   1024          // NKVH*HDIM
#define HEAVY 819           // int(1024*0.8)
#define RECENT 204          // int(1024*0.2)
#define NTOP  1844          // SEQ-RECENT
#define SP1   2049          // SEQ+1
#define ATT_SCALE 0.08838834764831843f

#define OUT0_ELEMS (SEQ * HIDN)
#define OUT1_ELEMS (NHEAD * SP1)

// ---------------- scratch (device globals: allocation-free) ----------------
__device__ float g_Q[(size_t)SEQ * HIDN];
__device__ float g_K[(size_t)SEQ * KVD];
__device__ float g_V[(size_t)SEQ * KVD];
__device__ float g_Q2[(size_t)SEQ * HIDN];          // roped Q
__device__ float g_K2[(size_t)SEQ * KVD];           // roped K
__device__ float g_AO[(size_t)SEQ * HIDN];
__device__ float g_colsum[NHEAD * SEQ];
__device__ float g_sink[SEQ * HIDN];
__device__ float g_S[(size_t)NHEAD * SEQ * SEQ];    // attn weights fp32

// bf16 split operands
__device__ __nv_bfloat16 g_Hhi[(size_t)SEQ * HIDN];
__device__ __nv_bfloat16 g_Hlo[(size_t)SEQ * HIDN];
__device__ __nv_bfloat16 g_AOhi[(size_t)SEQ * HIDN];
__device__ __nv_bfloat16 g_AOlo[(size_t)SEQ * HIDN];
__device__ __nv_bfloat16 g_Q2hi[(size_t)SEQ * HIDN];
__device__ __nv_bfloat16 g_Q2lo[(size_t)SEQ * HIDN];
__device__ __nv_bfloat16 g_K2hi[(size_t)SEQ * KVD];
__device__ __nv_bfloat16 g_K2lo[(size_t)SEQ * KVD];
__device__ __nv_bfloat16 g_Shi[(size_t)NHEAD * SEQ * SEQ];   // 268 MB
__device__ __nv_bfloat16 g_Slo[(size_t)NHEAD * SEQ * SEQ];   // 268 MB
__device__ __nv_bfloat16 g_Vthi[(size_t)NKVH * HDIM * SEQ];  // (g, d, s)
__device__ __nv_bfloat16 g_Vtlo[(size_t)NKVH * HDIM * SEQ];
__device__ __nv_bfloat16 g_WqThi[(size_t)HIDN * HIDN];       // [N, K] K-major
__device__ __nv_bfloat16 g_WqTlo[(size_t)HIDN * HIDN];
__device__ __nv_bfloat16 g_WkThi[(size_t)KVD * HIDN];
__device__ __nv_bfloat16 g_WkTlo[(size_t)KVD * HIDN];
__device__ __nv_bfloat16 g_WvThi[(size_t)KVD * HIDN];
__device__ __nv_bfloat16 g_WvTlo[(size_t)KVD * HIDN];
__device__ __nv_bfloat16 g_WoThi[(size_t)HIDN * HIDN];
__device__ __nv_bfloat16 g_WoTlo[(size_t)HIDN * HIDN];

// ---------------- mma helpers ----------------------------------------------
__device__ __forceinline__ void ldsm_x4(uint32_t& r0, uint32_t& r1,
                                        uint32_t& r2, uint32_t& r3, uint32_t addr) {
    asm volatile("ldmatrix.sync.aligned.m8n8.x4.shared.b16 {%0,%1,%2,%3}, [%4];"
                 : "=r"(r0), "=r"(r1), "=r"(r2), "=r"(r3) : "r"(addr));
}
__device__ __forceinline__ void ldsm_x2(uint32_t& r0, uint32_t& r1, uint32_t addr) {
    asm volatile("ldmatrix.sync.aligned.m8n8.x2.shared.b16 {%0,%1}, [%2];"
                 : "=r"(r0), "=r"(r1) : "r"(addr));
}
__device__ __forceinline__ void mma_bf16(float* d, const uint32_t* a, const uint32_t* b) {
    asm volatile(
        "mma.sync.aligned.m16n8k16.row.col.f32.bf16.bf16.f32 "
        "{%0,%1,%2,%3}, {%4,%5,%6,%7}, {%8,%9}, {%0,%1,%2,%3};"
        : "+f"(d[0]), "+f"(d[1]), "+f"(d[2]), "+f"(d[3])
        : "r"(a[0]), "r"(a[1]), "r"(a[2]), "r"(a[3]), "r"(b[0]), "r"(b[1]));
}

// ---------------- generalized fused split-bf16 tensor-core GEMM ------------
// C[z][m,n] = alpha * sum_k (Ahi+Alo)[z][m,k] * (Bhi+Blo)[z/bzDiv][n,k]
// mode 1: causal score (skip bx>by).  mode 2: causal AV (Keff=(by+1)*128).
#define LDS 40
__global__ void __launch_bounds__(256) mma3gemm_ex(
    const __nv_bfloat16* __restrict__ Ahi, const __nv_bfloat16* __restrict__ Alo,
    int lda, long long aZ,
    const __nv_bfloat16* __restrict__ Bhi, const __nv_bfloat16* __restrict__ Blo,
    int ldb, long long bZ, int bzDiv,
    float* __restrict__ C, int ldc, long long cZ,
    int K, float alpha, int mode)
{
    int bx = blockIdx.x, by = blockIdx.y, bz = blockIdx.z;
    if (mode == 1 && bx > by) return;
    int Keff = K;
    if (mode == 2) { int kl = (by + 1) * 128; if (kl < K) Keff = kl; }

    __shared__ __nv_bfloat16 sAhi[128 * LDS];
    __shared__ __nv_bfloat16 sAlo[128 * LDS];
    __shared__ __nv_bfloat16 sBhi[128 * LDS];
    __shared__ __nv_bfloat16 sBlo[128 * LDS];

    int tid  = threadIdx.x;
    int lane = tid & 31;
    int wid  = tid >> 5;
    int wm   = wid & 1;
    int wn   = wid >> 1;
    int m0 = by * 128;
    int n0 = bx * 128;

    int lr = tid >> 1;
    int lc = (tid & 1) * 16;
    const __nv_bfloat16* gAhi = Ahi + (size_t)bz * aZ + (size_t)(m0 + lr) * lda + lc;
    const __nv_bfloat16* gAlo = Alo + (size_t)bz * aZ + (size_t)(m0 + lr) * lda + lc;
    const __nv_bfloat16* gBhi = Bhi + (size_t)(bz / bzDiv) * bZ + (size_t)(n0 + lr) * ldb + lc;
    const __nv_bfloat16* gBlo = Blo + (size_t)(bz / bzDiv) * bZ + (size_t)(n0 + lr) * ldb + lc;
    uint32_t so = (uint32_t)(lr * LDS + lc) * 2;
    uint32_t bAhi = (uint32_t)__cvta_generic_to_shared(sAhi);
    uint32_t bAlo = (uint32_t)__cvta_generic_to_shared(sAlo);
    uint32_t bBhi = (uint32_t)__cvta_generic_to_shared(sBhi);
    uint32_t bBlo = (uint32_t)__cvta_generic_to_shared(sBlo);

    float d[4][4][4];
#pragma unroll
    for (int i = 0; i < 4; i++)
#pragma unroll
        for (int j = 0; j < 4; j++)
#pragma unroll
            for (int f = 0; f < 4; f++) d[i][j][f] = 0.f;

    int arow = wm * 64 + (lane & 15);
    int acol = (lane >> 4) * 8;
    int brow = wn * 32 + (lane & 7);
    int bcol = ((lane >> 3) & 1) * 8;

    int nchunks = Keff / 32;
    for (int c = 0; c < nchunks; c++) {
        *(uint4*)((char*)sAhi + so)      = *(const uint4*)(gAhi);
        *(uint4*)((char*)sAhi + so + 16) = *(const uint4*)(gAhi + 8);
        *(uint4*)((char*)sAlo + so)      = *(const uint4*)(gAlo);
        *(uint4*)((char*)sAlo + so + 16) = *(const uint4*)(gAlo + 8);
        *(uint4*)((char*)sBhi + so)      = *(const uint4*)(gBhi);
        *(uint4*)((char*)sBhi + so + 16) = *(const uint4*)(gBhi + 8);
        *(uint4*)((char*)sBlo + so)      = *(const uint4*)(gBlo);
        *(uint4*)((char*)sBlo + so + 16) = *(const uint4*)(gBlo + 8);
        gAhi += 32; gAlo += 32; gBhi += 32; gBlo += 32;
        __syncthreads();

#pragma unroll
        for (int ks = 0; ks < 2; ks++) {
            uint32_t bh[4][2], bl[4][2];
#pragma unroll
            for (int nt = 0; nt < 4; nt++) {
                uint32_t off = (uint32_t)((brow + nt * 8) * LDS + ks * 16 + bcol) * 2;
                ldsm_x2(bh[nt][0], bh[nt][1], bBhi + off);
                ldsm_x2(bl[nt][0], bl[nt][1], bBlo + off);
            }
#pragma unroll
            for (int mt = 0; mt < 4; mt++) {
                uint32_t off = (uint32_t)((arow + mt * 16) * LDS + ks * 16 + acol) * 2;
                uint32_t ah[4], al[4];
                ldsm_x4(ah[0], ah[1], ah[2], ah[3], bAhi + off);
                ldsm_x4(al[0], al[1], al[2], al[3], bAlo + off);
#pragma unroll
                for (int nt = 0; nt < 4; nt++) {
                    mma_bf16(d[mt][nt], ah, bh[nt]);
                    mma_bf16(d[mt][nt], ah, bl[nt]);
                    mma_bf16(d[mt][nt], al, bh[nt]);
                }
            }
        }
        __syncthreads();
    }

    int cr = lane >> 2;
    int cc = (lane & 3) * 2;
    float* Cz = C + (size_t)bz * cZ;
#pragma unroll
    for (int mt = 0; mt < 4; mt++) {
#pragma unroll
        for (int nt = 0; nt < 4; nt++) {
            float* base = Cz + (size_t)(m0 + wm * 64 + mt * 16 + cr) * ldc
                        + n0 + wn * 32 + nt * 8 + cc;
            base[0] = alpha * d[mt][nt][0];
            base[1] = alpha * d[mt][nt][1];
            base[(size_t)8 * ldc]     = alpha * d[mt][nt][2];
            base[(size_t)8 * ldc + 1] = alpha * d[mt][nt][3];
        }
    }
}

// ---------------- fp32 -> bf16 hi/lo split (elementwise) -------------------
__global__ void split_hl(const float* __restrict__ X,
                         __nv_bfloat16* __restrict__ Hi,
                         __nv_bfloat16* __restrict__ Lo, int n) {
    int i = blockIdx.x * blockDim.x + threadIdx.x;
    if (i >= n) return;
    float v = X[i];
    __nv_bfloat16 h = __float2bfloat16(v);
    Hi[i] = h;
    Lo[i] = __float2bfloat16(v - __bfloat162float(h));
}

// ---------------- W[K,N] -> WT[N,K] with hi/lo split -----------------------
__global__ void transpose_split(const float* __restrict__ W, int K, int N,
                                __nv_bfloat16* __restrict__ Thi,
                                __nv_bfloat16* __restrict__ Tlo) {
    __shared__ float t[32][33];
    int n0 = blockIdx.x * 32, k0 = blockIdx.y * 32;
    int tx = threadIdx.x, ty = threadIdx.y;
#pragma unroll
    for (int j = 0; j < 4; j++)
        t[ty + 8 * j][tx] = W[(size_t)(k0 + ty + 8 * j) * N + n0 + tx];
    __syncthreads();
#pragma unroll
    for (int j = 0; j < 4; j++) {
        float v = t[tx][ty + 8 * j];
        __nv_bfloat16 h = __float2bfloat16(v);
        size_t o = (size_t)(n0 + ty + 8 * j) * K + k0 + tx;
        Thi[o] = h;
        Tlo[o] = __float2bfloat16(v - __bfloat162float(h));
    }
}

// ---------------- V -> Vt per kv-head: g_Vt[g][d][s] hi/lo -----------------
__global__ void transpose_split_v() {
    __shared__ float t[32][33];
    int g  = blockIdx.z;
    int d0 = blockIdx.x * 32;
    int s0 = blockIdx.y * 32;
    int tx = threadIdx.x, ty = threadIdx.y;
#pragma unroll
    for (int j = 0; j < 4; j++)
        t[ty + 8 * j][tx] = g_V[(size_t)(s0 + ty + 8 * j) * KVD + g * HDIM + d0 + tx];
    __syncthreads();
#pragma unroll
    for (int j = 0; j < 4; j++) {
        float v = t[tx][ty + 8 * j];
        __nv_bfloat16 h = __float2bfloat16(v);
        size_t o = ((size_t)g * HDIM + d0 + ty + 8 * j) * SEQ + s0 + tx;
        g_Vthi[o] = h;
        g_Vtlo[o] = __float2bfloat16(v - __bfloat162float(h));
    }
}

// ---------------- RoPE v2 (FROZEN — proven correct in R9) ------------------
__global__ void rope2_kernel() {
    int s  = blockIdx.x;
    int hh = blockIdx.y;
    int i  = threadIdx.x;
    float invf = (float)pow(10000.0, -(double)i / 64.0);
    float ang  = (float)s * invf;
    float c  = (float)cos((double)ang);
    float sn = (float)sin((double)ang);
    const float* src;
    float* dst;
    if (hh < NHEAD) {
        src = g_Q  + (size_t)s * HIDN + hh * HDIM;
        dst = g_Q2 + (size_t)s * HIDN + hh * HDIM;
    } else {
        src = g_K  + (size_t)s * KVD + (hh - NHEAD) * HDIM;
        dst = g_K2 + (size_t)s * KVD + (hh - NHEAD) * HDIM;
    }
    float x0 = src[i], x1 = src[i + 64];
    dst[i]      = x0 * c - x1 * sn;
    dst[i + 64] = x1 * c + x0 * sn;
}

// ---------------- causal softmax (verified) --------------------------------
__global__ void softmax_tiled() {
    int q = blockIdx.x, h = blockIdx.y;
    float* row = g_S + ((size_t)h * SEQ + q) * SEQ;
    int len = q + 1;
    int t = threadIdx.x;
    __shared__ float red[256];
    float m = -INFINITY;
    for (int i = t; i < len; i += 256) m = fmaxf(m, row[i]);
    red[t] = m; __syncthreads();
    for (int sft = 128; sft > 0; sft >>= 1) {
        if (t < sft) red[t] = fmaxf(red[t], red[t + sft]);
        __syncthreads();
    }
    m = red[0]; __syncthreads();
    float sum = 0.f;
    for (int i = t; i < len; i += 256) {
        float e = expf(row[i] - m);
        row[i] = e;
        sum += e;
    }
    red[t] = sum; __syncthreads();
    for (int sft = 128; sft > 0; sft >>= 1) {
        if (t < sft) red[t] += red[t + sft];
        __syncthreads();
    }
    float inv = 1.0f / red[0];
    for (int i = t; i < len; i += 256) row[i] *= inv;
    for (int i = len + t; i < SEQ; i += 256) row[i] = 0.0f;
}

// ---------------- column sums (verified) -----------------------------------
__global__ void colsum_kernel() {
    int idx = blockIdx.x * blockDim.x + threadIdx.x;
    int h = idx >> 11;
    int k = idx & (SEQ - 1);
    const float* base = g_S + (size_t)h * SEQ * SEQ + k;
    float s = 0.0f;
    for (int q = k; q < SEQ; q++) s += base[(size_t)q * SEQ];
    g_colsum[idx] = s;
}

// ---------------- top-k heavy-hitter mask (verified) -----------------------
__global__ void topk_mask_kernel(float* __restrict__ out_mask) {
    __shared__ float sv[2048];
    __shared__ int   si[2048];
    int h = blockIdx.x;
    int t = threadIdx.x;
    for (int i = t; i < 2048; i += 1024) {
        sv[i] = (i < NTOP) ? g_colsum[h * SEQ + i] : -INFINITY;
        si[i] = i;
    }
    __syncthreads();
    for (int k = 2; k <= 2048; k <<= 1) {
        for (int j = k >> 1; j > 0; j >>= 1) {
            for (int i = t; i < 2048; i += 1024) {
                int ixj = i ^ j;
                if (ixj > i) {
                    bool dirDesc = ((i & k) == 0);
                    float v1 = sv[i], v2 = sv[ixj];
                    int i1 = si[i], i2 = si[ixj];
                    bool before = (v1 > v2) || (v1 == v2 && i1 < i2);
                    bool doSwap = dirDesc ? !before : before;
                    if (doSwap) { sv[i] = v2; sv[ixj] = v1; si[i] = i2; si[ixj] = i1; }
                }
            }
            __syncthreads();
        }
    }
    for (int j = t; j < SP1; j += 1024)
        out_mask[(size_t)h * SP1 + j] = (j >= SP1 - RECENT) ? 1.0f : 0.0f;
    __syncthreads();
    for (int r = t; r < HEAVY; r += 1024)
        out_mask[(size_t)h * SP1 + si[r]] = 1.0f;
}

// ---------------- launch --------------------------------------------------
extern "C" void kernel_launch(void* const* d_in, const int* in_sizes, int n_in,
                              void* d_out, int out_size) {
    const float *hidden = 0, *Wq = 0, *Wk = 0, *Wv = 0, *Wo = 0;
    for (int i = 0; i < n_in; i++) {
        int sz = in_sizes[i];
        const float* p = (const float*)d_in[i];
        if (sz == SEQ * HIDN)            { hidden = p; }
        else if (sz == HIDN * HIDN)      { if (!Wq) Wq = p; else Wo = p; }
        else if (sz == HIDN * KVD)       { if (!Wk) Wk = p; else Wv = p; }
    }

    float *pQ, *pK, *pV, *pQ2, *pK2, *pAO, *pS, *pSink;
    cudaGetSymbolAddress((void**)&pQ,  g_Q);
    cudaGetSymbolAddress((void**)&pK,  g_K);
    cudaGetSymbolAddress((void**)&pV,  g_V);
    cudaGetSymbolAddress((void**)&pQ2, g_Q2);
    cudaGetSymbolAddress((void**)&pK2, g_K2);
    cudaGetSymbolAddress((void**)&pAO, g_AO);
    cudaGetSymbolAddress((void**)&pS,  g_S);
    cudaGetSymbolAddress((void**)&pSink, g_sink);

    __nv_bfloat16 *pHhi, *pHlo, *pAOhi, *pAOlo, *pQ2hi, *pQ2lo, *pK2hi, *pK2lo;
    __nv_bfloat16 *pShi, *pSlo, *pVthi, *pVtlo;
    __nv_bfloat16 *pWqThi, *pWqTlo, *pWkThi, *pWkTlo, *pWvThi, *pWvTlo, *pWoThi, *pWoTlo;
    cudaGetSymbolAddress((void**)&pHhi,  g_Hhi);
    cudaGetSymbolAddress((void**)&pHlo,  g_Hlo);
    cudaGetSymbolAddress((void**)&pAOhi, g_AOhi);
    cudaGetSymbolAddress((void**)&pAOlo, g_AOlo);
    cudaGetSymbolAddress((void**)&pQ2hi, g_Q2hi);
    cudaGetSymbolAddress((void**)&pQ2lo, g_Q2lo);
    cudaGetSymbolAddress((void**)&pK2hi, g_K2hi);
    cudaGetSymbolAddress((void**)&pK2lo, g_K2lo);
    cudaGetSymbolAddress((void**)&pShi,  g_Shi);
    cudaGetSymbolAddress((void**)&pSlo,  g_Slo);
    cudaGetSymbolAddress((void**)&pVthi, g_Vthi);
    cudaGetSymbolAddress((void**)&pVtlo, g_Vtlo);
    cudaGetSymbolAddress((void**)&pWqThi, g_WqThi);
    cudaGetSymbolAddress((void**)&pWqTlo, g_WqTlo);
    cudaGetSymbolAddress((void**)&pWkThi, g_WkThi);
    cudaGetSymbolAddress((void**)&pWkTlo, g_WkTlo);
    cudaGetSymbolAddress((void**)&pWvThi, g_WvThi);
    cudaGetSymbolAddress((void**)&pWvTlo, g_WvTlo);
    cudaGetSymbolAddress((void**)&pWoThi, g_WoThi);
    cudaGetSymbolAddress((void**)&pWoTlo, g_WoTlo);

    // Output packing proven (R7): [attn | mask], attn at head.
    float* attn_dst = (float*)d_out;
    float* mask_dst;
    if (out_size == OUT0_ELEMS || out_size == OUT0_ELEMS * 4) {
        mask_dst = pSink;
    } else if (out_size == OUT1_ELEMS || out_size == OUT1_ELEMS * 4) {
        attn_dst = pSink;
        mask_dst = (float*)d_out;
    } else {
        mask_dst = (float*)d_out + OUT0_ELEMS;
    }

    dim3 tblk(32, 8);

    // 0. operand prep
    split_hl<<<(SEQ * HIDN + 255) / 256, 256>>>(hidden, pHhi, pHlo, SEQ * HIDN);
    transpose_split<<<dim3(HIDN / 32, HIDN / 32), tblk>>>(Wq, HIDN, HIDN, pWqThi, pWqTlo);
    transpose_split<<<dim3(KVD / 32,  HIDN / 32), tblk>>>(Wk, HIDN, KVD,  pWkThi, pWkTlo);
    transpose_split<<<dim3(KVD / 32,  HIDN / 32), tblk>>>(Wv, HIDN, KVD,  pWvThi, pWvTlo);
    transpose_split<<<dim3(HIDN / 32, HIDN / 32), tblk>>>(Wo, HIDN, HIDN, pWoThi, pWoTlo);

    // 1-3. QKV projections (mma3)
    mma3gemm_ex<<<dim3(HIDN / 128, SEQ / 128, 1), 256>>>(
        pHhi, pHlo, HIDN, 0, pWqThi, pWqTlo, HIDN, 0, 1, pQ, HIDN, 0, HIDN, 1.0f, 0);
    mma3gemm_ex<<<dim3(KVD / 128, SEQ / 128, 1), 256>>>(
        pHhi, pHlo, HIDN, 0, pWkThi, pWkTlo, HIDN, 0, 1, pK, KVD, 0, HIDN, 1.0f, 0);
    mma3gemm_ex<<<dim3(KVD / 128, SEQ / 128, 1), 256>>>(
        pHhi, pHlo, HIDN, 0, pWvThi, pWvTlo, HIDN, 0, 1, pV, KVD, 0, HIDN, 1.0f, 0);

    // 4. RoPE v2 (frozen) + V transpose-split
    rope2_kernel<<<dim3(SEQ, NHEAD + NKVH), 64>>>();
    transpose_split_v<<<dim3(HDIM / 32, SEQ / 32, NKVH), tblk>>>();

    // 5. split roped Q/K; scores via batched mma3 (causal tile skip)
    split_hl<<<(SEQ * HIDN + 255) / 256, 256>>>(pQ2, pQ2hi, pQ2lo, SEQ * HIDN);
    split_hl<<<(SEQ * KVD + 255) / 256, 256>>>(pK2, pK2hi, pK2lo, SEQ * KVD);
    mma3gemm_ex<<<dim3(SEQ / 128, SEQ / 128, NHEAD), 256>>>(
        pQ2hi, pQ2lo, HIDN, HDIM,
        pK2hi, pK2lo, KVD, HDIM, 4,
        pS, SEQ, (long long)SEQ * SEQ,
        HDIM, ATT_SCALE, 1);

    // 6. causal softmax
    softmax_tiled<<<dim3(SEQ, NHEAD), 256>>>();

    // 7. column sums
    colsum_kernel<<<(NHEAD * SEQ) / 256, 256>>>();

    // 8. AV via batched mma3 (split S; causal K-limit)
    split_hl<<<(NHEAD * SEQ * SEQ + 255) / 256, 256>>>(pS, pShi, pSlo, NHEAD * SEQ * SEQ);
    mma3gemm_ex<<<dim3(HDIM / 128, SEQ / 128, NHEAD), 256>>>(
        pShi, pSlo, SEQ, (long long)SEQ * SEQ,
        pVthi, pVtlo, SEQ, (long long)HDIM * SEQ, 4,
        pAO, HIDN, HDIM,
        SEQ, 1.0f, 2);

    // 9. heavy-hitter mask
    topk_mask_kernel<<<NHEAD, 1024>>>(mask_dst);

    // 10. output projection (split AO, mma3)
    split_hl<<<(SEQ * HIDN + 255) / 256, 256>>>(pAO, pAOhi, pAOlo, SEQ * HIDN);
    mma3gemm_ex<<<dim3(HIDN / 128, SEQ / 128, 1), 256>>>(
        pAOhi, pAOlo, HIDN, 0, pWoThi, pWoTlo, HIDN, 0, 1,
        attn_dst, HIDN, 0, HIDN, 1.0f, 0);
}

// round 16
// speedup vs baseline: 12.6293x; 1.1352x over previous
#include <cuda_runtime.h>
#include <cuda_bf16.h>
#include <math.h>
#include <stdint.h>

#define SEQ   2048
#define HIDN  4096
#define NHEAD 32
#define NKVH  8
#define HDIM  128
#define KVD   1024          // NKVH*HDIM
#define HEAVY 819           // int(1024*0.8)
#define RECENT 204          // int(1024*0.2)
#define NTOP  1844          // SEQ-RECENT
#define SP1   2049          // SEQ+1
#define ATT_SCALE 0.08838834764831843f

#define OUT0_ELEMS (SEQ * HIDN)
#define OUT1_ELEMS (NHEAD * SP1)

// ---------------- scratch (device globals: allocation-free) ----------------
__device__ float g_Q[(size_t)SEQ * HIDN];
__device__ float g_K[(size_t)SEQ * KVD];
__device__ float g_V[(size_t)SEQ * KVD];
__device__ float g_Q2[(size_t)SEQ * HIDN];          // roped Q
__device__ float g_K2[(size_t)SEQ * KVD];           // roped K
__device__ float g_AO[(size_t)SEQ * HIDN];
__device__ float g_colsum[NHEAD * SEQ];
__device__ float g_sink[SEQ * HIDN];
__device__ float g_S[(size_t)NHEAD * SEQ * SEQ];    // pre-softmax scores fp32

// bf16 split operands
__device__ __nv_bfloat16 g_Hhi[(size_t)SEQ * HIDN];
__device__ __nv_bfloat16 g_Hlo[(size_t)SEQ * HIDN];
__device__ __nv_bfloat16 g_AOhi[(size_t)SEQ * HIDN];
__device__ __nv_bfloat16 g_AOlo[(size_t)SEQ * HIDN];
__device__ __nv_bfloat16 g_Q2hi[(size_t)SEQ * HIDN];
__device__ __nv_bfloat16 g_Q2lo[(size_t)SEQ * HIDN];
__device__ __nv_bfloat16 g_K2hi[(size_t)SEQ * KVD];
__device__ __nv_bfloat16 g_K2lo[(size_t)SEQ * KVD];
__device__ __nv_bfloat16 g_Shi[(size_t)NHEAD * SEQ * SEQ];   // softmax weights hi
__device__ __nv_bfloat16 g_Slo[(size_t)NHEAD * SEQ * SEQ];   // softmax weights lo
__device__ __nv_bfloat16 g_Vthi[(size_t)NKVH * HDIM * SEQ];  // (g, d, s)
__device__ __nv_bfloat16 g_Vtlo[(size_t)NKVH * HDIM * SEQ];
__device__ __nv_bfloat16 g_WqThi[(size_t)HIDN * HIDN];       // [N, K] K-major
__device__ __nv_bfloat16 g_WqTlo[(size_t)HIDN * HIDN];
__device__ __nv_bfloat16 g_WkThi[(size_t)KVD * HIDN];
__device__ __nv_bfloat16 g_WkTlo[(size_t)KVD * HIDN];
__device__ __nv_bfloat16 g_WvThi[(size_t)KVD * HIDN];
__device__ __nv_bfloat16 g_WvTlo[(size_t)KVD * HIDN];
__device__ __nv_bfloat16 g_WoThi[(size_t)HIDN * HIDN];
__device__ __nv_bfloat16 g_WoTlo[(size_t)HIDN * HIDN];

// ---------------- mma / async helpers ---------------------------------------
__device__ __forceinline__ void ldsm_x4(uint32_t& r0, uint32_t& r1,
                                        uint32_t& r2, uint32_t& r3, uint32_t addr) {
    asm volatile("ldmatrix.sync.aligned.m8n8.x4.shared.b16 {%0,%1,%2,%3}, [%4];"
                 : "=r"(r0), "=r"(r1), "=r"(r2), "=r"(r3) : "r"(addr));
}
__device__ __forceinline__ void ldsm_x2(uint32_t& r0, uint32_t& r1, uint32_t addr) {
    asm volatile("ldmatrix.sync.aligned.m8n8.x2.shared.b16 {%0,%1}, [%2];"
                 : "=r"(r0), "=r"(r1) : "r"(addr));
}
__device__ __forceinline__ void mma_bf16(float* d, const uint32_t* a, const uint32_t* b) {
    asm volatile(
        "mma.sync.aligned.m16n8k16.row.col.f32.bf16.bf16.f32 "
        "{%0,%1,%2,%3}, {%4,%5,%6,%7}, {%8,%9}, {%0,%1,%2,%3};"
        : "+f"(d[0]), "+f"(d[1]), "+f"(d[2]), "+f"(d[3])
        : "r"(a[0]), "r"(a[1]), "r"(a[2]), "r"(a[3]), "r"(b[0]), "r"(b[1]));
}
__device__ __forceinline__ void cp16(uint32_t saddr, const void* gptr) {
    asm volatile("cp.async.cg.shared.global [%0], [%1], 16;"
                 :: "r"(saddr), "l"(gptr));
}
#define CP_COMMIT() asm volatile("cp.async.commit_group;" ::: "memory")
#define CP_WAIT1()  asm volatile("cp.async.wait_group 1;" ::: "memory")
#define CP_WAIT0()  asm volatile("cp.async.wait_group 0;" ::: "memory")

// ---------------- generalized fused split-bf16 tensor-core GEMM ------------
// C[z][m,n] = alpha * sum_k (Ahi+Alo)[z][m,k] * (Bhi+Blo)[z/bzDiv][n,k]
// mode 1: causal score (skip bx>by).  mode 2: causal AV (Keff=(by+1)*128).
// 2-stage cp.async pipeline, dynamic smem = 2 stages x 4 tiles x 128 x LDS bf16.
#define LDS 40
#define TILE_B (128 * LDS * 2)         // bytes per tile (10240)
#define SMEM_PIPE (2 * 4 * TILE_B)     // 81920 bytes
__global__ void __launch_bounds__(256) mma3gemm_ex(
    const __nv_bfloat16* __restrict__ Ahi, const __nv_bfloat16* __restrict__ Alo,
    int lda, long long aZ,
    const __nv_bfloat16* __restrict__ Bhi, const __nv_bfloat16* __restrict__ Blo,
    int ldb, long long bZ, int bzDiv,
    float* __restrict__ C, int ldc, long long cZ,
    int K, float alpha, int mode)
{
    extern __shared__ __nv_bfloat16 smbuf[];
    int bx = blockIdx.x, by = blockIdx.y, bz = blockIdx.z;
    if (mode == 1 && bx > by) return;
    int Keff = K;
    if (mode == 2) { int kl = (by + 1) * 128; if (kl < K) Keff = kl; }

    int tid  = threadIdx.x;
    int lane = tid & 31;
    int wid  = tid >> 5;
    int wm   = wid & 1;
    int wn   = wid >> 1;
    int m0 = by * 128;
    int n0 = bx * 128;

    int lr = tid >> 1;
    int lc = (tid & 1) * 16;
    const __nv_bfloat16* gAhi = Ahi + (size_t)bz * aZ + (size_t)(m0 + lr) * lda + lc;
    const __nv_bfloat16* gAlo = Alo + (size_t)bz * aZ + (size_t)(m0 + lr) * lda + lc;
    const __nv_bfloat16* gBhi = Bhi + (size_t)(bz / bzDiv) * bZ + (size_t)(n0 + lr) * ldb + lc;
    const __nv_bfloat16* gBlo = Blo + (size_t)(bz / bzDiv) * bZ + (size_t)(n0 + lr) * ldb + lc;
    uint32_t so = (uint32_t)(lr * LDS + lc) * 2;
    uint32_t sbase = (uint32_t)__cvta_generic_to_shared(smbuf);

    float d[4][4][4];
#pragma unroll
    for (int i = 0; i < 4; i++)
#pragma unroll
        for (int j = 0; j < 4; j++)
#pragma unroll
            for (int f = 0; f < 4; f++) d[i][j][f] = 0.f;

    int arow = wm * 64 + (lane & 15);
    int acol = (lane >> 4) * 8;
    int brow = wn * 32 + (lane & 7);
    int bcol = ((lane >> 3) & 1) * 8;

    int nchunks = Keff / 32;

    // async load of chunk c into stage st
    auto load_chunk = [&](int c, int st) {
        uint32_t b = sbase + (uint32_t)st * 4 * TILE_B;
        const __nv_bfloat16* pa = gAhi + (size_t)c * 32;
        const __nv_bfloat16* pb = gAlo + (size_t)c * 32;
        const __nv_bfloat16* pc = gBhi + (size_t)c * 32;
        const __nv_bfloat16* pd = gBlo + (size_t)c * 32;
        cp16(b + 0 * TILE_B + so,      pa);
        cp16(b + 0 * TILE_B + so + 16, pa + 8);
        cp16(b + 1 * TILE_B + so,      pb);
        cp16(b + 1 * TILE_B + so + 16, pb + 8);
        cp16(b + 2 * TILE_B + so,      pc);
        cp16(b + 2 * TILE_B + so + 16, pc + 8);
        cp16(b + 3 * TILE_B + so,      pd);
        cp16(b + 3 * TILE_B + so + 16, pd + 8);
    };

    // prologue
    load_chunk(0, 0);
    CP_COMMIT();

    for (int c = 0; c < nchunks; c++) {
        if (c + 1 < nchunks) {
            load_chunk(c + 1, (c + 1) & 1);
            CP_COMMIT();
            CP_WAIT1();
        } else {
            CP_WAIT0();
        }
        __syncthreads();

        uint32_t sb = sbase + (uint32_t)(c & 1) * 4 * TILE_B;
        uint32_t bAhi = sb;
        uint32_t bAlo = sb + TILE_B;
        uint32_t bBhi = sb + 2 * TILE_B;
        uint32_t bBlo = sb + 3 * TILE_B;

#pragma unroll
        for (int ks = 0; ks < 2; ks++) {
            uint32_t bh[4][2], bl[4][2];
#pragma unroll
            for (int nt = 0; nt < 4; nt++) {
                uint32_t off = (uint32_t)((brow + nt * 8) * LDS + ks * 16 + bcol) * 2;
                ldsm_x2(bh[nt][0], bh[nt][1], bBhi + off);
                ldsm_x2(bl[nt][0], bl[nt][1], bBlo + off);
            }
#pragma unroll
            for (int mt = 0; mt < 4; mt++) {
                uint32_t off = (uint32_t)((arow + mt * 16) * LDS + ks * 16 + acol) * 2;
                uint32_t ah[4], al[4];
                ldsm_x4(ah[0], ah[1], ah[2], ah[3], bAhi + off);
                ldsm_x4(al[0], al[1], al[2], al[3], bAlo + off);
#pragma unroll
                for (int nt = 0; nt < 4; nt++) {
                    mma_bf16(d[mt][nt], ah, bh[nt]);
                    mma_bf16(d[mt][nt], ah, bl[nt]);
                    mma_bf16(d[mt][nt], al, bh[nt]);
                }
            }
        }
        __syncthreads();   // stage (c&1) free for reuse at c+2
    }

    int cr = lane >> 2;
    int cc = (lane & 3) * 2;
    float* Cz = C + (size_t)bz * cZ;
#pragma unroll
    for (int mt = 0; mt < 4; mt++) {
#pragma unroll
        for (int nt = 0; nt < 4; nt++) {
            float* base = Cz + (size_t)(m0 + wm * 64 + mt * 16 + cr) * ldc
                        + n0 + wn * 32 + nt * 8 + cc;
            base[0] = alpha * d[mt][nt][0];
            base[1] = alpha * d[mt][nt][1];
            base[(size_t)8 * ldc]     = alpha * d[mt][nt][2];
            base[(size_t)8 * ldc + 1] = alpha * d[mt][nt][3];
        }
    }
}

// ---------------- fp32 -> bf16 hi/lo split (elementwise) -------------------
__global__ void split_hl(const float* __restrict__ X,
                         __nv_bfloat16* __restrict__ Hi,
                         __nv_bfloat16* __restrict__ Lo, int n) {
    int i = blockIdx.x * blockDim.x + threadIdx.x;
    if (i >= n) return;
    float v = X[i];
    __nv_bfloat16 h = __float2bfloat16(v);
    Hi[i] = h;
    Lo[i] = __float2bfloat16(v - __bfloat162float(h));
}

// ---------------- W[K,N] -> WT[N,K] with hi/lo split -----------------------
__global__ void transpose_split(const float* __restrict__ W, int K, int N,
                                __nv_bfloat16* __restrict__ Thi,
                                __nv_bfloat16* __restrict__ Tlo) {
    __shared__ float t[32][33];
    int n0 = blockIdx.x * 32, k0 = blockIdx.y * 32;
    int tx = threadIdx.x, ty = threadIdx.y;
#pragma unroll
    for (int j = 0; j < 4; j++)
        t[ty + 8 * j][tx] = W[(size_t)(k0 + ty + 8 * j) * N + n0 + tx];
    __syncthreads();
#pragma unroll
    for (int j = 0; j < 4; j++) {
        float v = t[tx][ty + 8 * j];
        __nv_bfloat16 h = __float2bfloat16(v);
        size_t o = (size_t)(n0 + ty + 8 * j) * K + k0 + tx;
        Thi[o] = h;
        Tlo[o] = __float2bfloat16(v - __bfloat162float(h));
    }
}

// ---------------- V -> Vt per kv-head: g_Vt[g][d][s] hi/lo -----------------
__global__ void transpose_split_v() {
    __shared__ float t[32][33];
    int g  = blockIdx.z;
    int d0 = blockIdx.x * 32;
    int s0 = blockIdx.y * 32;
    int tx = threadIdx.x, ty = threadIdx.y;
#pragma unroll
    for (int j = 0; j < 4; j++)
        t[ty + 8 * j][tx] = g_V[(size_t)(s0 + ty + 8 * j) * KVD + g * HDIM + d0 + tx];
    __syncthreads();
#pragma unroll
    for (int j = 0; j < 4; j++) {
        float v = t[tx][ty + 8 * j];
        __nv_bfloat16 h = __float2bfloat16(v);
        size_t o = ((size_t)g * HDIM + d0 + ty + 8 * j) * SEQ + s0 + tx;
        g_Vthi[o] = h;
        g_Vtlo[o] = __float2bfloat16(v - __bfloat162float(h));
    }
}

// ---------------- RoPE v2 (FROZEN — proven correct in R9) ------------------
__global__ void rope2_kernel() {
    int s  = blockIdx.x;
    int hh = blockIdx.y;
    int i  = threadIdx.x;
    float invf = (float)pow(10000.0, -(double)i / 64.0);
    float ang  = (float)s * invf;
    float c  = (float)cos((double)ang);
    float sn = (float)sin((double)ang);
    const float* src;
    float* dst;
    if (hh < NHEAD) {
        src = g_Q  + (size_t)s * HIDN + hh * HDIM;
        dst = g_Q2 + (size_t)s * HIDN + hh * HDIM;
    } else {
        src = g_K  + (size_t)s * KVD + (hh - NHEAD) * HDIM;
        dst = g_K2 + (size_t)s * KVD + (hh - NHEAD) * HDIM;
    }
    float x0 = src[i], x1 = src[i + 64];
    dst[i]      = x0 * c - x1 * sn;
    dst[i + 64] = x1 * c + x0 * sn;
}

// ---------------- causal softmax + fused bf16 hi/lo split ------------------
// Reads fp32 scores, writes normalized weights DIRECTLY as bf16 hi/lo.
// Arithmetic identical to prior softmax+split (w = e * inv, same fp32 ops).
__global__ void softmax_split() {
    int q = blockIdx.x, h = blockIdx.y;
    const float* row = g_S + ((size_t)h * SEQ + q) * SEQ;
    __nv_bfloat16* hrow = g_Shi + ((size_t)h * SEQ + q) * SEQ;
    __nv_bfloat16* lrow = g_Slo + ((size_t)h * SEQ + q) * SEQ;
    int len = q + 1;
    int t = threadIdx.x;
    __shared__ float red[256];
    float m = -INFINITY;
    for (int i = t; i < len; i += 256) m = fmaxf(m, row[i]);
    red[t] = m; __syncthreads();
    for (int sft = 128; sft > 0; sft >>= 1) {
        if (t < sft) red[t] = fmaxf(red[t], red[t + sft]);
        __syncthreads();
    }
    m = red[0]; __syncthreads();
    float sum = 0.f;
    for (int i = t; i < len; i += 256) sum += expf(row[i] - m);
    red[t] = sum; __syncthreads();
    for (int sft = 128; sft > 0; sft >>= 1) {
        if (t < sft) red[t] += red[t + sft];
        __syncthreads();
    }
    float inv = 1.0f / red[0];
    __nv_bfloat16 z = __float2bfloat16(0.0f);
    for (int i = t; i < len; i += 256) {
        float w = expf(row[i] - m) * inv;
        __nv_bfloat16 hi = __float2bfloat16(w);
        hrow[i] = hi;
        lrow[i] = __float2bfloat16(w - __bfloat162float(hi));
    }
    for (int i = len + t; i < SEQ; i += 256) { hrow[i] = z; lrow[i] = z; }
}

// ---------------- column sums from hi+lo weights ---------------------------
__global__ void colsum_kernel() {
    int idx = blockIdx.x * blockDim.x + threadIdx.x;
    int h = idx >> 11;
    int k = idx & (SEQ - 1);
    const __nv_bfloat16* hb = g_Shi + (size_t)h * SEQ * SEQ + k;
    const __nv_bfloat16* lb = g_Slo + (size_t)h * SEQ * SEQ + k;
    float s = 0.0f;
    for (int q = k; q < SEQ; q++)
        s += __bfloat162float(hb[(size_t)q * SEQ]) + __bfloat162float(lb[(size_t)q * SEQ]);
    g_colsum[idx] = s;
}

// ---------------- top-k heavy-hitter mask (verified) -----------------------
__global__ void topk_mask_kernel(float* __restrict__ out_mask) {
    __shared__ float sv[2048];
    __shared__ int   si[2048];
    int h = blockIdx.x;
    int t = threadIdx.x;
    for (int i = t; i < 2048; i += 1024) {
        sv[i] = (i < NTOP) ? g_colsum[h * SEQ + i] : -INFINITY;
        si[i] = i;
    }
    __syncthreads();
    for (int k = 2; k <= 2048; k <<= 1) {
        for (int j = k >> 1; j > 0; j >>= 1) {
            for (int i = t; i < 2048; i += 1024) {
                int ixj = i ^ j;
                if (ixj > i) {
                    bool dirDesc = ((i & k) == 0);
                    float v1 = sv[i], v2 = sv[ixj];
                    int i1 = si[i], i2 = si[ixj];
                    bool before = (v1 > v2) || (v1 == v2 && i1 < i2);
                    bool doSwap = dirDesc ? !before : before;
                    if (doSwap) { sv[i] = v2; sv[ixj] = v1; si[i] = i2; si[ixj] = i1; }
                }
            }
            __syncthreads();
        }
    }
    for (int j = t; j < SP1; j += 1024)
        out_mask[(size_t)h * SP1 + j] = (j >= SP1 - RECENT) ? 1.0f : 0.0f;
    __syncthreads();
    for (int r = t; r < HEAVY; r += 1024)
        out_mask[(size_t)h * SP1 + si[r]] = 1.0f;
}

// ---------------- launch --------------------------------------------------
extern "C" void kernel_launch(void* const* d_in, const int* in_sizes, int n_in,
                              void* d_out, int out_size) {
    const float *hidden = 0, *Wq = 0, *Wk = 0, *Wv = 0, *Wo = 0;
    for (int i = 0; i < n_in; i++) {
        int sz = in_sizes[i];
        const float* p = (const float*)d_in[i];
        if (sz == SEQ * HIDN)            { hidden = p; }
        else if (sz == HIDN * HIDN)      { if (!Wq) Wq = p; else Wo = p; }
        else if (sz == HIDN * KVD)       { if (!Wk) Wk = p; else Wv = p; }
    }

    float *pQ, *pK, *pV, *pQ2, *pK2, *pAO, *pS, *pSink;
    cudaGetSymbolAddress((void**)&pQ,  g_Q);
    cudaGetSymbolAddress((void**)&pK,  g_K);
    cudaGetSymbolAddress((void**)&pV,  g_V);
    cudaGetSymbolAddress((void**)&pQ2, g_Q2);
    cudaGetSymbolAddress((void**)&pK2, g_K2);
    cudaGetSymbolAddress((void**)&pAO, g_AO);
    cudaGetSymbolAddress((void**)&pS,  g_S);
    cudaGetSymbolAddress((void**)&pSink, g_sink);

    __nv_bfloat16 *pHhi, *pHlo, *pAOhi, *pAOlo, *pQ2hi, *pQ2lo, *pK2hi, *pK2lo;
    __nv_bfloat16 *pShi, *pSlo, *pVthi, *pVtlo;
    __nv_bfloat16 *pWqThi, *pWqTlo, *pWkThi, *pWkTlo, *pWvThi, *pWvTlo, *pWoThi, *pWoTlo;
    cudaGetSymbolAddress((void**)&pHhi,  g_Hhi);
    cudaGetSymbolAddress((void**)&pHlo,  g_Hlo);
    cudaGetSymbolAddress((void**)&pAOhi, g_AOhi);
    cudaGetSymbolAddress((void**)&pAOlo, g_AOlo);
    cudaGetSymbolAddress((void**)&pQ2hi, g_Q2hi);
    cudaGetSymbolAddress((void**)&pQ2lo, g_Q2lo);
    cudaGetSymbolAddress((void**)&pK2hi, g_K2hi);
    cudaGetSymbolAddress((void**)&pK2lo, g_K2lo);
    cudaGetSymbolAddress((void**)&pShi,  g_Shi);
    cudaGetSymbolAddress((void**)&pSlo,  g_Slo);
    cudaGetSymbolAddress((void**)&pVthi, g_Vthi);
    cudaGetSymbolAddress((void**)&pVtlo, g_Vtlo);
    cudaGetSymbolAddress((void**)&pWqThi, g_WqThi);
    cudaGetSymbolAddress((void**)&pWqTlo, g_WqTlo);
    cudaGetSymbolAddress((void**)&pWkThi, g_WkThi);
    cudaGetSymbolAddress((void**)&pWkTlo, g_WkTlo);
    cudaGetSymbolAddress((void**)&pWvThi, g_WvThi);
    cudaGetSymbolAddress((void**)&pWvTlo, g_WvTlo);
    cudaGetSymbolAddress((void**)&pWoThi, g_WoThi);
    cudaGetSymbolAddress((void**)&pWoTlo, g_WoTlo);

    // Output packing proven (R7): [attn | mask], attn at head.
    float* attn_dst = (float*)d_out;
    float* mask_dst;
    if (out_size == OUT0_ELEMS || out_size == OUT0_ELEMS * 4) {
        mask_dst = pSink;
    } else if (out_size == OUT1_ELEMS || out_size == OUT1_ELEMS * 4) {
        attn_dst = pSink;
        mask_dst = (float*)d_out;
    } else {
        mask_dst = (float*)d_out + OUT0_ELEMS;
    }

    // allow 80KB dynamic smem for the pipelined gemm (idempotent, not an alloc)
    static int smem_set = 0;
    if (!smem_set) {
        cudaFuncSetAttribute(mma3gemm_ex,
                             cudaFuncAttributeMaxDynamicSharedMemorySize, SMEM_PIPE);
        smem_set = 1;
    }

    dim3 tblk(32, 8);

    // 0. operand prep
    split_hl<<<(SEQ * HIDN + 255) / 256, 256>>>(hidden, pHhi, pHlo, SEQ * HIDN);
    transpose_split<<<dim3(HIDN / 32, HIDN / 32), tblk>>>(Wq, HIDN, HIDN, pWqThi, pWqTlo);
    transpose_split<<<dim3(KVD / 32,  HIDN / 32), tblk>>>(Wk, HIDN, KVD,  pWkThi, pWkTlo);
    transpose_split<<<dim3(KVD / 32,  HIDN / 32), tblk>>>(Wv, HIDN, KVD,  pWvThi, pWvTlo);
    transpose_split<<<dim3(HIDN / 32, HIDN / 32), tblk>>>(Wo, HIDN, HIDN, pWoThi, pWoTlo);

    // 1-3. QKV projections (mma3, pipelined)
    mma3gemm_ex<<<dim3(HIDN / 128, SEQ / 128, 1), 256, SMEM_PIPE>>>(
        pHhi, pHlo, HIDN, 0, pWqThi, pWqTlo, HIDN, 0, 1, pQ, HIDN, 0, HIDN, 1.0f, 0);
    mma3gemm_ex<<<dim3(KVD / 128, SEQ / 128, 1), 256, SMEM_PIPE>>>(
        pHhi, pHlo, HIDN, 0, pWkThi, pWkTlo, HIDN, 0, 1, pK, KVD, 0, HIDN, 1.0f, 0);
    mma3gemm_ex<<<dim3(KVD / 128, SEQ / 128, 1), 256, SMEM_PIPE>>>(
        pHhi, pHlo, HIDN, 0, pWvThi, pWvTlo, HIDN, 0, 1, pV, KVD, 0, HIDN, 1.0f, 0);

    // 4. RoPE v2 (frozen) + V transpose-split
    rope2_kernel<<<dim3(SEQ, NHEAD + NKVH), 64>>>();
    transpose_split_v<<<dim3(HDIM / 32, SEQ / 32, NKVH), tblk>>>();

    // 5. split roped Q/K; scores via batched mma3 (causal tile skip)
    split_hl<<<(SEQ * HIDN + 255) / 256, 256>>>(pQ2, pQ2hi, pQ2lo, SEQ * HIDN);
    split_hl<<<(SEQ * KVD + 255) / 256, 256>>>(pK2, pK2hi, pK2lo, SEQ * KVD);
    mma3gemm_ex<<<dim3(SEQ / 128, SEQ / 128, NHEAD), 256, SMEM_PIPE>>>(
        pQ2hi, pQ2lo, HIDN, HDIM,
        pK2hi, pK2lo, KVD, HDIM, 4,
        pS, SEQ, (long long)SEQ * SEQ,
        HDIM, ATT_SCALE, 1);

    // 6. causal softmax with fused bf16 hi/lo output (split_S eliminated)
    softmax_split<<<dim3(SEQ, NHEAD), 256>>>();

    // 7. column sums (reconstruct hi+lo)
    colsum_kernel<<<(NHEAD * SEQ) / 256, 256>>>();

    // 8. AV via batched mma3 (causal K-limit)
    mma3gemm_ex<<<dim3(HDIM / 128, SEQ / 128, NHEAD), 256, SMEM_PIPE>>>(
        pShi, pSlo, SEQ, (long long)SEQ * SEQ,
        pVthi, pVtlo, SEQ, (long long)HDIM * SEQ, 4,
        pAO, HIDN, HDIM,
        SEQ, 1.0f, 2);

    // 9. heavy-hitter mask
    topk_mask_kernel<<<NHEAD, 1024>>>(mask_dst);

    // 10. output projection (split AO, mma3)
    split_hl<<<(SEQ * HIDN + 255) / 256, 256>>>(pAO, pAOhi, pAOlo, SEQ * HIDN);
    mma3gemm_ex<<<dim3(HIDN / 128, SEQ / 128, 1), 256, SMEM_PIPE>>>(
        pAOhi, pAOlo, HIDN, 0, pWoThi, pWoTlo, HIDN, 0, 1,
        attn_dst, HIDN, 0, HIDN, 1.0f, 0);
}

// round 17
// speedup vs baseline: 12.9193x; 1.0230x over previous
#include <cuda_runtime.h>
#include <cuda_bf16.h>
#include <math.h>
#include <stdint.h>

#define SEQ   2048
#define HIDN  4096
#define NHEAD 32
#define NKVH  8
#define HDIM  128
#define KVD   1024          // NKVH*HDIM
#define KV2   2048          // combined K|V width
#define HEAVY 819
#define RECENT 204
#define NTOP  1844
#define SP1   2049
#define ATT_SCALE 0.08838834764831843f

#define OUT0_ELEMS (SEQ * HIDN)
#define OUT1_ELEMS (NHEAD * SP1)

// ---------------- scratch (device globals: allocation-free) ----------------
__device__ float g_Q[(size_t)SEQ * HIDN];
__device__ float g_KV[(size_t)SEQ * KV2];           // [s][K(0:1024)|V(1024:2048)]
__device__ float g_Q2[(size_t)SEQ * HIDN];          // roped Q
__device__ float g_K2[(size_t)SEQ * KVD];           // roped K
__device__ float g_AO[(size_t)SEQ * HIDN];
__device__ float g_colsum[NHEAD * SEQ];
__device__ float g_sink[SEQ * HIDN];
__device__ float g_S[(size_t)NHEAD * SEQ * SEQ];    // pre-softmax scores fp32

// bf16 split operands
__device__ __nv_bfloat16 g_Hhi[(size_t)SEQ * HIDN];
__device__ __nv_bfloat16 g_Hlo[(size_t)SEQ * HIDN];
__device__ __nv_bfloat16 g_AOhi[(size_t)SEQ * HIDN];
__device__ __nv_bfloat16 g_AOlo[(size_t)SEQ * HIDN];
__device__ __nv_bfloat16 g_Q2hi[(size_t)SEQ * HIDN];
__device__ __nv_bfloat16 g_Q2lo[(size_t)SEQ * HIDN];
__device__ __nv_bfloat16 g_K2hi[(size_t)SEQ * KVD];
__device__ __nv_bfloat16 g_K2lo[(size_t)SEQ * KVD];
__device__ __nv_bfloat16 g_Shi[(size_t)NHEAD * SEQ * SEQ];
__device__ __nv_bfloat16 g_Slo[(size_t)NHEAD * SEQ * SEQ];
__device__ __nv_bfloat16 g_Vthi[(size_t)NKVH * HDIM * SEQ];
__device__ __nv_bfloat16 g_Vtlo[(size_t)NKVH * HDIM * SEQ];
__device__ __nv_bfloat16 g_WqThi[(size_t)HIDN * HIDN];       // [N, K] K-major
__device__ __nv_bfloat16 g_WqTlo[(size_t)HIDN * HIDN];
__device__ __nv_bfloat16 g_WkvThi[(size_t)KV2 * HIDN];       // K rows 0:1024, V 1024:2048
__device__ __nv_bfloat16 g_WkvTlo[(size_t)KV2 * HIDN];
__device__ __nv_bfloat16 g_WoThi[(size_t)HIDN * HIDN];
__device__ __nv_bfloat16 g_WoTlo[(size_t)HIDN * HIDN];

// ---------------- mma / async helpers ---------------------------------------
__device__ __forceinline__ void ldsm_x4(uint32_t& r0, uint32_t& r1,
                                        uint32_t& r2, uint32_t& r3, uint32_t addr) {
    asm volatile("ldmatrix.sync.aligned.m8n8.x4.shared.b16 {%0,%1,%2,%3}, [%4];"
                 : "=r"(r0), "=r"(r1), "=r"(r2), "=r"(r3) : "r"(addr));
}
__device__ __forceinline__ void ldsm_x2(uint32_t& r0, uint32_t& r1, uint32_t addr) {
    asm volatile("ldmatrix.sync.aligned.m8n8.x2.shared.b16 {%0,%1}, [%2];"
                 : "=r"(r0), "=r"(r1) : "r"(addr));
}
__device__ __forceinline__ void mma_bf16(float* d, const uint32_t* a, const uint32_t* b) {
    asm volatile(
        "mma.sync.aligned.m16n8k16.row.col.f32.bf16.bf16.f32 "
        "{%0,%1,%2,%3}, {%4,%5,%6,%7}, {%8,%9}, {%0,%1,%2,%3};"
        : "+f"(d[0]), "+f"(d[1]), "+f"(d[2]), "+f"(d[3])
        : "r"(a[0]), "r"(a[1]), "r"(a[2]), "r"(a[3]), "r"(b[0]), "r"(b[1]));
}
__device__ __forceinline__ void cp16(uint32_t saddr, const void* gptr) {
    asm volatile("cp.async.cg.shared.global [%0], [%1], 16;"
                 :: "r"(saddr), "l"(gptr));
}
#define CP_COMMIT() asm volatile("cp.async.commit_group;" ::: "memory")
#define CP_WAIT1()  asm volatile("cp.async.wait_group 1;" ::: "memory")
#define CP_WAIT0()  asm volatile("cp.async.wait_group 0;" ::: "memory")

#define LDS 40
// ---------------- 128x128 pipelined mma3 gemm (verified; scores/AV) --------
#define TILE_B (128 * LDS * 2)
#define SMEM_PIPE (2 * 4 * TILE_B)      // 81920
__global__ void __launch_bounds__(256) mma3gemm_ex(
    const __nv_bfloat16* __restrict__ Ahi, const __nv_bfloat16* __restrict__ Alo,
    int lda, long long aZ,
    const __nv_bfloat16* __restrict__ Bhi, const __nv_bfloat16* __restrict__ Blo,
    int ldb, long long bZ, int bzDiv,
    float* __restrict__ C, int ldc, long long cZ,
    int K, float alpha, int mode)
{
    extern __shared__ __nv_bfloat16 smbuf[];
    int bx = blockIdx.x, by = blockIdx.y, bz = blockIdx.z;
    if (mode == 1 && bx > by) return;
    int Keff = K;
    if (mode == 2) { int kl = (by + 1) * 128; if (kl < K) Keff = kl; }

    int tid  = threadIdx.x;
    int lane = tid & 31;
    int wid  = tid >> 5;
    int wm   = wid & 1;
    int wn   = wid >> 1;
    int m0 = by * 128;
    int n0 = bx * 128;

    int lr = tid >> 1;
    int lc = (tid & 1) * 16;
    const __nv_bfloat16* gAhi = Ahi + (size_t)bz * aZ + (size_t)(m0 + lr) * lda + lc;
    const __nv_bfloat16* gAlo = Alo + (size_t)bz * aZ + (size_t)(m0 + lr) * lda + lc;
    const __nv_bfloat16* gBhi = Bhi + (size_t)(bz / bzDiv) * bZ + (size_t)(n0 + lr) * ldb + lc;
    const __nv_bfloat16* gBlo = Blo + (size_t)(bz / bzDiv) * bZ + (size_t)(n0 + lr) * ldb + lc;
    uint32_t so = (uint32_t)(lr * LDS + lc) * 2;
    uint32_t sbase = (uint32_t)__cvta_generic_to_shared(smbuf);

    float d[4][4][4];
#pragma unroll
    for (int i = 0; i < 4; i++)
#pragma unroll
        for (int j = 0; j < 4; j++)
#pragma unroll
            for (int f = 0; f < 4; f++) d[i][j][f] = 0.f;

    int arow = wm * 64 + (lane & 15);
    int acol = (lane >> 4) * 8;
    int brow = wn * 32 + (lane & 7);
    int bcol = ((lane >> 3) & 1) * 8;

    int nchunks = Keff / 32;
    auto load_chunk = [&](int c, int st) {
        uint32_t b = sbase + (uint32_t)st * 4 * TILE_B;
        const __nv_bfloat16* pa = gAhi + (size_t)c * 32;
        const __nv_bfloat16* pb = gAlo + (size_t)c * 32;
        const __nv_bfloat16* pc = gBhi + (size_t)c * 32;
        const __nv_bfloat16* pd = gBlo + (size_t)c * 32;
        cp16(b + 0 * TILE_B + so,      pa);
        cp16(b + 0 * TILE_B + so + 16, pa + 8);
        cp16(b + 1 * TILE_B + so,      pb);
        cp16(b + 1 * TILE_B + so + 16, pb + 8);
        cp16(b + 2 * TILE_B + so,      pc);
        cp16(b + 2 * TILE_B + so + 16, pc + 8);
        cp16(b + 3 * TILE_B + so,      pd);
        cp16(b + 3 * TILE_B + so + 16, pd + 8);
    };

    load_chunk(0, 0);
    CP_COMMIT();

    for (int c = 0; c < nchunks; c++) {
        if (c + 1 < nchunks) {
            load_chunk(c + 1, (c + 1) & 1);
            CP_COMMIT();
            CP_WAIT1();
        } else {
            CP_WAIT0();
        }
        __syncthreads();

        uint32_t sb = sbase + (uint32_t)(c & 1) * 4 * TILE_B;
        uint32_t bAhi = sb;
        uint32_t bAlo = sb + TILE_B;
        uint32_t bBhi = sb + 2 * TILE_B;
        uint32_t bBlo = sb + 3 * TILE_B;

#pragma unroll
        for (int ks = 0; ks < 2; ks++) {
            uint32_t bh[4][2], bl[4][2];
#pragma unroll
            for (int nt = 0; nt < 4; nt++) {
                uint32_t off = (uint32_t)((brow + nt * 8) * LDS + ks * 16 + bcol) * 2;
                ldsm_x2(bh[nt][0], bh[nt][1], bBhi + off);
                ldsm_x2(bl[nt][0], bl[nt][1], bBlo + off);
            }
#pragma unroll
            for (int mt = 0; mt < 4; mt++) {
                uint32_t off = (uint32_t)((arow + mt * 16) * LDS + ks * 16 + acol) * 2;
                uint32_t ah[4], al[4];
                ldsm_x4(ah[0], ah[1], ah[2], ah[3], bAhi + off);
                ldsm_x4(al[0], al[1], al[2], al[3], bAlo + off);
#pragma unroll
                for (int nt = 0; nt < 4; nt++) {
                    mma_bf16(d[mt][nt], ah, bh[nt]);
                    mma_bf16(d[mt][nt], ah, bl[nt]);
                    mma_bf16(d[mt][nt], al, bh[nt]);
                }
            }
        }
        __syncthreads();
    }

    int cr = lane >> 2;
    int cc = (lane & 3) * 2;
    float* Cz = C + (size_t)bz * cZ;
#pragma unroll
    for (int mt = 0; mt < 4; mt++) {
#pragma unroll
        for (int nt = 0; nt < 4; nt++) {
            float* base = Cz + (size_t)(m0 + wm * 64 + mt * 16 + cr) * ldc
                        + n0 + wn * 32 + nt * 8 + cc;
            base[0] = alpha * d[mt][nt][0];
            base[1] = alpha * d[mt][nt][1];
            base[(size_t)8 * ldc]     = alpha * d[mt][nt][2];
            base[(size_t)8 * ldc + 1] = alpha * d[mt][nt][3];
        }
    }
}

// ---------------- 256x128 big-tile pipelined mma3 gemm (projections) -------
// 8 warps: wm = wid&3 (64-row block), wn = wid>>2 (64-col block); 64x64/warp.
#define ATILE_B (256 * LDS * 2)          // 20480
#define BTILE_B (128 * LDS * 2)          // 10240
#define STAGE_B (2 * ATILE_B + 2 * BTILE_B)   // 61440
#define SMEM_BIG (2 * STAGE_B)                // 122880
__global__ void __launch_bounds__(256, 1) mma3gemm_big(
    const __nv_bfloat16* __restrict__ Ahi, const __nv_bfloat16* __restrict__ Alo,
    const __nv_bfloat16* __restrict__ Bhi, const __nv_bfloat16* __restrict__ Blo,
    float* __restrict__ C, int K, int ldc)
{
    extern __shared__ __nv_bfloat16 smbuf[];
    int tid  = threadIdx.x;
    int lane = tid & 31;
    int wid  = tid >> 5;
    int wm   = wid & 3;
    int wn   = wid >> 2;
    int m0 = blockIdx.y * 256;
    int n0 = blockIdx.x * 128;

    int lr = tid >> 1;                 // 0..127
    int lc = (tid & 1) * 16;
    const __nv_bfloat16* gAhi = Ahi + (size_t)(m0 + lr) * K + lc;   // + row 128 later
    const __nv_bfloat16* gAlo = Alo + (size_t)(m0 + lr) * K + lc;
    const __nv_bfloat16* gBhi = Bhi + (size_t)(n0 + lr) * K + lc;
    const __nv_bfloat16* gBlo = Blo + (size_t)(n0 + lr) * K + lc;
    size_t arstep = (size_t)128 * K;   // +128 rows for A
    uint32_t soA0 = (uint32_t)(lr * LDS + lc) * 2;
    uint32_t soA1 = (uint32_t)((lr + 128) * LDS + lc) * 2;
    uint32_t soB  = soA0;
    uint32_t sbase = (uint32_t)__cvta_generic_to_shared(smbuf);

    float d[4][8][4];
#pragma unroll
    for (int i = 0; i < 4; i++)
#pragma unroll
        for (int j = 0; j < 8; j++)
#pragma unroll
            for (int f = 0; f < 4; f++) d[i][j][f] = 0.f;

    int arow = wm * 64 + (lane & 15);
    int acol = (lane >> 4) * 8;
    int brow = wn * 64 + (lane & 7);
    int bcol = ((lane >> 3) & 1) * 8;

    int nchunks = K / 32;
    auto load_chunk = [&](int c, int st) {
        uint32_t b = sbase + (uint32_t)st * STAGE_B;
        const __nv_bfloat16* pa = gAhi + (size_t)c * 32;
        const __nv_bfloat16* pb = gAlo + (size_t)c * 32;
        const __nv_bfloat16* pc = gBhi + (size_t)c * 32;
        const __nv_bfloat16* pd = gBlo + (size_t)c * 32;
        // A hi (256 rows)
        cp16(b + soA0,      pa);
        cp16(b + soA0 + 16, pa + 8);
        cp16(b + soA1,      pa + arstep);
        cp16(b + soA1 + 16, pa + arstep + 8);
        // A lo
        uint32_t b2 = b + ATILE_B;
        cp16(b2 + soA0,      pb);
        cp16(b2 + soA0 + 16, pb + 8);
        cp16(b2 + soA1,      pb + arstep);
        cp16(b2 + soA1 + 16, pb + arstep + 8);
        // B hi / lo (128 rows)
        uint32_t b3 = b + 2 * ATILE_B;
        cp16(b3 + soB,      pc);
        cp16(b3 + soB + 16, pc + 8);
        uint32_t b4 = b3 + BTILE_B;
        cp16(b4 + soB,      pd);
        cp16(b4 + soB + 16, pd + 8);
    };

    load_chunk(0, 0);
    CP_COMMIT();

    for (int c = 0; c < nchunks; c++) {
        if (c + 1 < nchunks) {
            load_chunk(c + 1, (c + 1) & 1);
            CP_COMMIT();
            CP_WAIT1();
        } else {
            CP_WAIT0();
        }
        __syncthreads();

        uint32_t sb = sbase + (uint32_t)(c & 1) * STAGE_B;
        uint32_t bAhi = sb;
        uint32_t bAlo = sb + ATILE_B;
        uint32_t bBhi = sb + 2 * ATILE_B;
        uint32_t bBlo = bBhi + BTILE_B;

#pragma unroll
        for (int ks = 0; ks < 2; ks++) {
            uint32_t bh[8][2], bl[8][2];
#pragma unroll
            for (int nt = 0; nt < 8; nt++) {
                uint32_t off = (uint32_t)((brow + nt * 8) * LDS + ks * 16 + bcol) * 2;
                ldsm_x2(bh[nt][0], bh[nt][1], bBhi + off);
                ldsm_x2(bl[nt][0], bl[nt][1], bBlo + off);
            }
#pragma unroll
            for (int mt = 0; mt < 4; mt++) {
                uint32_t off = (uint32_t)((arow + mt * 16) * LDS + ks * 16 + acol) * 2;
                uint32_t ah[4], al[4];
                ldsm_x4(ah[0], ah[1], ah[2], ah[3], bAhi + off);
                ldsm_x4(al[0], al[1], al[2], al[3], bAlo + off);
#pragma unroll
                for (int nt = 0; nt < 8; nt++) {
                    mma_bf16(d[mt][nt], ah, bh[nt]);
                    mma_bf16(d[mt][nt], ah, bl[nt]);
                    mma_bf16(d[mt][nt], al, bh[nt]);
                }
            }
        }
        __syncthreads();
    }

    int cr = lane >> 2;
    int cc = (lane & 3) * 2;
#pragma unroll
    for (int mt = 0; mt < 4; mt++) {
#pragma unroll
        for (int nt = 0; nt < 8; nt++) {
            float* base = C + (size_t)(m0 + wm * 64 + mt * 16 + cr) * ldc
                        + n0 + wn * 64 + nt * 8 + cc;
            base[0] = d[mt][nt][0];
            base[1] = d[mt][nt][1];
            base[(size_t)8 * ldc]     = d[mt][nt][2];
            base[(size_t)8 * ldc + 1] = d[mt][nt][3];
        }
    }
}

// ---------------- fp32 -> bf16 hi/lo split ---------------------------------
__global__ void split_hl(const float* __restrict__ X,
                         __nv_bfloat16* __restrict__ Hi,
                         __nv_bfloat16* __restrict__ Lo, int n) {
    int i = blockIdx.x * blockDim.x + threadIdx.x;
    if (i >= n) return;
    float v = X[i];
    __nv_bfloat16 h = __float2bfloat16(v);
    Hi[i] = h;
    Lo[i] = __float2bfloat16(v - __bfloat162float(h));
}

// ---------------- W[K,N] -> WT[N,K] with hi/lo split -----------------------
__global__ void transpose_split(const float* __restrict__ W, int K, int N,
                                __nv_bfloat16* __restrict__ Thi,
                                __nv_bfloat16* __restrict__ Tlo) {
    __shared__ float t[32][33];
    int n0 = blockIdx.x * 32, k0 = blockIdx.y * 32;
    int tx = threadIdx.x, ty = threadIdx.y;
#pragma unroll
    for (int j = 0; j < 4; j++)
        t[ty + 8 * j][tx] = W[(size_t)(k0 + ty + 8 * j) * N + n0 + tx];
    __syncthreads();
#pragma unroll
    for (int j = 0; j < 4; j++) {
        float v = t[tx][ty + 8 * j];
        __nv_bfloat16 h = __float2bfloat16(v);
        size_t o = (size_t)(n0 + ty + 8 * j) * K + k0 + tx;
        Thi[o] = h;
        Tlo[o] = __float2bfloat16(v - __bfloat162float(h));
    }
}

// ---------------- V (cols 1024:2048 of g_KV) -> Vt hi/lo -------------------
__global__ void transpose_split_v() {
    __shared__ float t[32][33];
    int g  = blockIdx.z;
    int d0 = blockIdx.x * 32;
    int s0 = blockIdx.y * 32;
    int tx = threadIdx.x, ty = threadIdx.y;
#pragma unroll
    for (int j = 0; j < 4; j++)
        t[ty + 8 * j][tx] = g_KV[(size_t)(s0 + ty + 8 * j) * KV2 + KVD + g * HDIM + d0 + tx];
    __syncthreads();
#pragma unroll
    for (int j = 0; j < 4; j++) {
        float v = t[tx][ty + 8 * j];
        __nv_bfloat16 h = __float2bfloat16(v);
        size_t o = ((size_t)g * HDIM + d0 + ty + 8 * j) * SEQ + s0 + tx;
        g_Vthi[o] = h;
        g_Vtlo[o] = __float2bfloat16(v - __bfloat162float(h));
    }
}

// ---------------- RoPE v2 (FROZEN math; K source now in g_KV) --------------
__global__ void rope2_kernel() {
    int s  = blockIdx.x;
    int hh = blockIdx.y;
    int i  = threadIdx.x;
    float invf = (float)pow(10000.0, -(double)i / 64.0);
    float ang  = (float)s * invf;
    float c  = (float)cos((double)ang);
    float sn = (float)sin((double)ang);
    const float* src;
    float* dst;
    if (hh < NHEAD) {
        src = g_Q  + (size_t)s * HIDN + hh * HDIM;
        dst = g_Q2 + (size_t)s * HIDN + hh * HDIM;
    } else {
        src = g_KV + (size_t)s * KV2 + (hh - NHEAD) * HDIM;   // K cols 0:1024
        dst = g_K2 + (size_t)s * KVD + (hh - NHEAD) * HDIM;
    }
    float x0 = src[i], x1 = src[i + 64];
    dst[i]      = x0 * c - x1 * sn;
    dst[i + 64] = x1 * c + x0 * sn;
}

// ---------------- causal softmax, register-resident, bf16 hi/lo out --------
// <=8 elems/thread; single gmem read of the score row. Zero-fill only to the
// AV tile boundary ((q>>7)+1)*128.
__global__ void softmax_split() {
    int q = blockIdx.x, h = blockIdx.y;
    const float* row = g_S + ((size_t)h * SEQ + q) * SEQ;
    __nv_bfloat16* hrow = g_Shi + ((size_t)h * SEQ + q) * SEQ;
    __nv_bfloat16* lrow = g_Slo + ((size_t)h * SEQ + q) * SEQ;
    int len = q + 1;
    int t = threadIdx.x;
    __shared__ float red[256];

    float r[8];
    int cnt = 0;
#pragma unroll
    for (int j = 0; j < 8; j++) {
        int i = t + j * 256;
        if (i < len) { r[j] = row[i]; cnt = j + 1; }
    }
    float m = -INFINITY;
#pragma unroll
    for (int j = 0; j < 8; j++)
        if (j < cnt) m = fmaxf(m, r[j]);
    red[t] = m; __syncthreads();
    for (int sft = 128; sft > 0; sft >>= 1) {
        if (t < sft) red[t] = fmaxf(red[t], red[t + sft]);
        __syncthreads();
    }
    m = red[0]; __syncthreads();
    float e[8];
    float sum = 0.f;
#pragma unroll
    for (int j = 0; j < 8; j++)
        if (j < cnt) { e[j] = expf(r[j] - m); sum += e[j]; }
    red[t] = sum; __syncthreads();
    for (int sft = 128; sft > 0; sft >>= 1) {
        if (t < sft) red[t] += red[t + sft];
        __syncthreads();
    }
    float inv = 1.0f / red[0];
#pragma unroll
    for (int j = 0; j < 8; j++) {
        int i = t + j * 256;
        if (j < cnt) {
            float w = e[j] * inv;
            __nv_bfloat16 hi = __float2bfloat16(w);
            hrow[i] = hi;
            lrow[i] = __float2bfloat16(w - __bfloat162float(hi));
        }
    }
    int zmax = ((q >> 7) + 1) << 7;           // AV Keff boundary
    __nv_bfloat16 z = __float2bfloat16(0.0f);
    for (int i = len + t; i < zmax; i += 256) { hrow[i] = z; lrow[i] = z; }
}

// ---------------- column sums from hi+lo weights ---------------------------
__global__ void colsum_kernel() {
    int idx = blockIdx.x * blockDim.x + threadIdx.x;
    int h = idx >> 11;
    int k = idx & (SEQ - 1);
    const __nv_bfloat16* hb = g_Shi + (size_t)h * SEQ * SEQ + k;
    const __nv_bfloat16* lb = g_Slo + (size_t)h * SEQ * SEQ + k;
    float s = 0.0f;
    for (int q = k; q < SEQ; q++)
        s += __bfloat162float(hb[(size_t)q * SEQ]) + __bfloat162float(lb[(size_t)q * SEQ]);
    g_colsum[idx] = s;
}

// ---------------- top-k heavy-hitter mask (verified) -----------------------
__global__ void topk_mask_kernel(float* __restrict__ out_mask) {
    __shared__ float sv[2048];
    __shared__ int   si[2048];
    int h = blockIdx.x;
    int t = threadIdx.x;
    for (int i = t; i < 2048; i += 1024) {
        sv[i] = (i < NTOP) ? g_colsum[h * SEQ + i] : -INFINITY;
        si[i] = i;
    }
    __syncthreads();
    for (int k = 2; k <= 2048; k <<= 1) {
        for (int j = k >> 1; j > 0; j >>= 1) {
            for (int i = t; i < 2048; i += 1024) {
                int ixj = i ^ j;
                if (ixj > i) {
                    bool dirDesc = ((i & k) == 0);
                    float v1 = sv[i], v2 = sv[ixj];
                    int i1 = si[i], i2 = si[ixj];
                    bool before = (v1 > v2) || (v1 == v2 && i1 < i2);
                    bool doSwap = dirDesc ? !before : before;
                    if (doSwap) { sv[i] = v2; sv[ixj] = v1; si[i] = i2; si[ixj] = i1; }
                }
            }
            __syncthreads();
        }
    }
    for (int j = t; j < SP1; j += 1024)
        out_mask[(size_t)h * SP1 + j] = (j >= SP1 - RECENT) ? 1.0f : 0.0f;
    __syncthreads();
    for (int r = t; r < HEAVY; r += 1024)
        out_mask[(size_t)h * SP1 + si[r]] = 1.0f;
}

// ---------------- launch --------------------------------------------------
extern "C" void kernel_launch(void* const* d_in, const int* in_sizes, int n_in,
                              void* d_out, int out_size) {
    const float *hidden = 0, *Wq = 0, *Wk = 0, *Wv = 0, *Wo = 0;
    for (int i = 0; i < n_in; i++) {
        int sz = in_sizes[i];
        const float* p = (const float*)d_in[i];
        if (sz == SEQ * HIDN)            { hidden = p; }
        else if (sz == HIDN * HIDN)      { if (!Wq) Wq = p; else Wo = p; }
        else if (sz == HIDN * KVD)       { if (!Wk) Wk = p; else Wv = p; }
    }

    float *pQ, *pKV, *pQ2, *pK2, *pAO, *pS, *pSink;
    cudaGetSymbolAddress((void**)&pQ,  g_Q);
    cudaGetSymbolAddress((void**)&pKV, g_KV);
    cudaGetSymbolAddress((void**)&pQ2, g_Q2);
    cudaGetSymbolAddress((void**)&pK2, g_K2);
    cudaGetSymbolAddress((void**)&pAO, g_AO);
    cudaGetSymbolAddress((void**)&pS,  g_S);
    cudaGetSymbolAddress((void**)&pSink, g_sink);

    __nv_bfloat16 *pHhi, *pHlo, *pAOhi, *pAOlo, *pQ2hi, *pQ2lo, *pK2hi, *pK2lo;
    __nv_bfloat16 *pShi, *pSlo, *pVthi, *pVtlo;
    __nv_bfloat16 *pWqThi, *pWqTlo, *pWkvThi, *pWkvTlo, *pWoThi, *pWoTlo;
    cudaGetSymbolAddress((void**)&pHhi,  g_Hhi);
    cudaGetSymbolAddress((void**)&pHlo,  g_Hlo);
    cudaGetSymbolAddress((void**)&pAOhi, g_AOhi);
    cudaGetSymbolAddress((void**)&pAOlo, g_AOlo);
    cudaGetSymbolAddress((void**)&pQ2hi, g_Q2hi);
    cudaGetSymbolAddress((void**)&pQ2lo, g_Q2lo);
    cudaGetSymbolAddress((void**)&pK2hi, g_K2hi);
    cudaGetSymbolAddress((void**)&pK2lo, g_K2lo);
    cudaGetSymbolAddress((void**)&pShi,  g_Shi);
    cudaGetSymbolAddress((void**)&pSlo,  g_Slo);
    cudaGetSymbolAddress((void**)&pVthi, g_Vthi);
    cudaGetSymbolAddress((void**)&pVtlo, g_Vtlo);
    cudaGetSymbolAddress((void**)&pWqThi,  g_WqThi);
    cudaGetSymbolAddress((void**)&pWqTlo,  g_WqTlo);
    cudaGetSymbolAddress((void**)&pWkvThi, g_WkvThi);
    cudaGetSymbolAddress((void**)&pWkvTlo, g_WkvTlo);
    cudaGetSymbolAddress((void**)&pWoThi,  g_WoThi);
    cudaGetSymbolAddress((void**)&pWoTlo,  g_WoTlo);

    // Output packing proven (R7): [attn | mask], attn at head.
    float* attn_dst = (float*)d_out;
    float* mask_dst;
    if (out_size == OUT0_ELEMS || out_size == OUT0_ELEMS * 4) {
        mask_dst = pSink;
    } else if (out_size == OUT1_ELEMS || out_size == OUT1_ELEMS * 4) {
        attn_dst = pSink;
        mask_dst = (float*)d_out;
    } else {
        mask_dst = (float*)d_out + OUT0_ELEMS;
    }

    static int smem_set = 0;
    if (!smem_set) {
        cudaFuncSetAttribute(mma3gemm_ex,
                             cudaFuncAttributeMaxDynamicSharedMemorySize, SMEM_PIPE);
        cudaFuncSetAttribute(mma3gemm_big,
                             cudaFuncAttributeMaxDynamicSharedMemorySize, SMEM_BIG);
        smem_set = 1;
    }

    dim3 tblk(32, 8);

    // 0. operand prep (Wk, Wv -> combined WkvT rows 0:1024 / 1024:2048)
    split_hl<<<(SEQ * HIDN + 255) / 256, 256>>>(hidden, pHhi, pHlo, SEQ * HIDN);
    transpose_split<<<dim3(HIDN / 32, HIDN / 32), tblk>>>(Wq, HIDN, HIDN, pWqThi, pWqTlo);
    transpose_split<<<dim3(KVD / 32,  HIDN / 32), tblk>>>(Wk, HIDN, KVD, pWkvThi, pWkvTlo);
    transpose_split<<<dim3(KVD / 32,  HIDN / 32), tblk>>>(
        Wv, HIDN, KVD, pWkvThi + (size_t)KVD * HIDN, pWkvTlo + (size_t)KVD * HIDN);
    transpose_split<<<dim3(HIDN / 32, HIDN / 32), tblk>>>(Wo, HIDN, HIDN, pWoThi, pWoTlo);

    // 1-2. Q projection + fused KV projection (big-tile gemm)
    mma3gemm_big<<<dim3(HIDN / 128, SEQ / 256), 256, SMEM_BIG>>>(
        pHhi, pHlo, pWqThi, pWqTlo, pQ, HIDN, HIDN);
    mma3gemm_big<<<dim3(KV2 / 128, SEQ / 256), 256, SMEM_BIG>>>(
        pHhi, pHlo, pWkvThi, pWkvTlo, pKV, HIDN, KV2);

    // 3. RoPE v2 + V transpose-split
    rope2_kernel<<<dim3(SEQ, NHEAD + NKVH), 64>>>();
    transpose_split_v<<<dim3(HDIM / 32, SEQ / 32, NKVH), tblk>>>();

    // 4. split roped Q/K; scores via batched mma3 (causal tile skip)
    split_hl<<<(SEQ * HIDN + 255) / 256, 256>>>(pQ2, pQ2hi, pQ2lo, SEQ * HIDN);
    split_hl<<<(SEQ * KVD + 255) / 256, 256>>>(pK2, pK2hi, pK2lo, SEQ * KVD);
    mma3gemm_ex<<<dim3(SEQ / 128, SEQ / 128, NHEAD), 256, SMEM_PIPE>>>(
        pQ2hi, pQ2lo, HIDN, HDIM,
        pK2hi, pK2lo, KVD, HDIM, 4,
        pS, SEQ, (long long)SEQ * SEQ,
        HDIM, ATT_SCALE, 1);

    // 5. register softmax with fused bf16 hi/lo output
    softmax_split<<<dim3(SEQ, NHEAD), 256>>>();

    // 6. column sums
    colsum_kernel<<<(NHEAD * SEQ) / 256, 256>>>();

    // 7. AV via batched mma3 (causal K-limit)
    mma3gemm_ex<<<dim3(HDIM / 128, SEQ / 128, NHEAD), 256, SMEM_PIPE>>>(
        pShi, pSlo, SEQ, (long long)SEQ * SEQ,
        pVthi, pVtlo, SEQ, (long long)HDIM * SEQ, 4,
        pAO, HIDN, HDIM,
        SEQ, 1.0f, 2);

    // 8. heavy-hitter mask
    topk_mask_kernel<<<NHEAD, 1024>>>(mask_dst);

    // 9. output projection (split AO, big-tile gemm)
    split_hl<<<(SEQ * HIDN + 255) / 256, 256>>>(pAO, pAOhi, pAOlo, SEQ * HIDN);
    mma3gemm_big<<<dim3(HIDN / 128, SEQ / 256), 256, SMEM_BIG>>>(
        pAOhi, pAOlo, pWoThi, pWoTlo, attn_dst, HIDN, HIDN);
}